// round 9
// baseline (speedup 1.0000x reference)
#include <cuda_runtime.h>
#include <cuda_bf16.h>
#include <math.h>
#include <stdint.h>

// Problem constants
#define BQ    8192
#define DQ    1024
#define HQ    4096
#define H2Q   2048
#define DOUTQ 1024
#define EQ    8
#define GQ    512
#define PAIRS (BQ * 2)

// ---------------- scratch (device globals) ---------------------------------
__device__ float g_g[BQ * GQ];
__device__ float g_y [PAIRS * DOUTQ];
__device__ float g_gatew[BQ * EQ];
__device__ int   g_topidx[BQ * 2];
__device__ float g_topw [BQ * 2];
__device__ int   g_cnt[EQ];
__device__ int   g_off[EQ + 1];
__device__ int   g_cursor[EQ];
__device__ int   g_ptok[PAIRS];
__device__ int   g_pidx[BQ * 2];
__device__ float g_usage[EQ];
__device__ int   g_gate_off[1] = {0};
__device__ int   g_gate_cnt[1] = {BQ};

// bf16 hi/lo split operands
__device__ __nv_bfloat16 g_xh[BQ * DQ];
__device__ __nv_bfloat16 g_xl[BQ * DQ];
__device__ __nv_bfloat16 g_w1h[EQ * DQ * HQ];
__device__ __nv_bfloat16 g_w1l[EQ * DQ * HQ];
__device__ __nv_bfloat16 g_w2h[EQ * HQ * H2Q];
__device__ __nv_bfloat16 g_w2l[EQ * HQ * H2Q];
__device__ __nv_bfloat16 g_w3h[EQ * H2Q * DOUTQ];
__device__ __nv_bfloat16 g_w3l[EQ * H2Q * DOUTQ];
__device__ __nv_bfloat16 g_h1h[PAIRS * HQ];
__device__ __nv_bfloat16 g_h1l[PAIRS * HQ];
__device__ __nv_bfloat16 g_h2h[PAIRS * H2Q];
__device__ __nv_bfloat16 g_h2l[PAIRS * H2Q];

// ---------------- helpers ---------------------------------------------------
__device__ __forceinline__ uint32_t smem_u32(const void* p) {
    uint32_t a;
    asm("{ .reg .u64 t; cvta.to.shared.u64 t, %1; cvt.u32.u64 %0, t; }"
        : "=r"(a) : "l"(p));
    return a;
}
__device__ __forceinline__ uint32_t sw64(uint32_t off) {
    return off ^ ((off >> 3) & 0x30);
}
__device__ __forceinline__ void ldsm_x4(uint32_t* r, uint32_t addr) {
    asm volatile("ldmatrix.sync.aligned.m8n8.x4.shared.b16 {%0,%1,%2,%3}, [%4];"
                 : "=r"(r[0]), "=r"(r[1]), "=r"(r[2]), "=r"(r[3]) : "r"(addr));
}
__device__ __forceinline__ void mma_bf16(float* d, const uint32_t* a,
                                         uint32_t b0, uint32_t b1) {
    asm volatile(
        "mma.sync.aligned.m16n8k16.row.col.f32.bf16.bf16.f32 "
        "{%0,%1,%2,%3}, {%4,%5,%6,%7}, {%8,%9}, {%0,%1,%2,%3};"
        : "+f"(d[0]), "+f"(d[1]), "+f"(d[2]), "+f"(d[3])
        : "r"(a[0]), "r"(a[1]), "r"(a[2]), "r"(a[3]), "r"(b0), "r"(b1));
}
__device__ __forceinline__ void cpa16(uint32_t d, const void* s) {
    asm volatile("cp.async.cg.shared.global [%0], [%1], 16;" :: "r"(d), "l"(s));
}
#define CP_COMMIT() asm volatile("cp.async.commit_group;" ::: "memory")
#define CP_WAIT1()  asm volatile("cp.async.wait_group 1;" ::: "memory")
#define CP_WAIT0()  asm volatile("cp.async.wait_group 0;" ::: "memory")

// ---------------- 3xBF16 pipelined segmented GEMM ---------------------------
// C[gm, n0..n0+128) = act(A[row(gm),:] @ B_e^T + bias_e)
// CTA tile 128Mx128N, K-chunk 32, 256 threads (4M x 2N warps), 3-stage cp.async,
// 2 CTAs/SM. smem rows 64B with SW64 swizzle.
// MMA schedule: 3 passes of 16 distinct accumulators (RAW distance 16).
#define TM 128
#define TN 128
#define TK 32
#define O_AH   0                 // 128*32*2 = 8192 bytes per half
#define O_AL   8192
#define O_BH   16384
#define O_BL   24576
#define STG_SZ 32768
#define SMEM_SZ (3 * STG_SZ)     // 98304

__global__ __launch_bounds__(256, 2) void moe_bf16_gemm3(
    const __nv_bfloat16* __restrict__ Ah, const __nv_bfloat16* __restrict__ Al,
    const __nv_bfloat16* __restrict__ Bh, const __nv_bfloat16* __restrict__ Bl,
    const float* __restrict__ bias,
    __nv_bfloat16* __restrict__ Ch, __nv_bfloat16* __restrict__ Cl,
    float* __restrict__ Cf,
    const int* __restrict__ rowmap,
    const int* __restrict__ seg_off,
    const int* __restrict__ seg_cnt,
    int K, int N, int relu)
{
    extern __shared__ char smem[];
    const int e    = blockIdx.z;
    const int mseg = seg_off[e];
    const int mend = mseg + seg_cnt[e];
    const int m0   = mseg + blockIdx.y * TM;
    if (m0 >= mend) return;
    const int n0 = blockIdx.x * TN;

    const long wbase = (long)e * (long)N * (long)K;
    const __nv_bfloat16* Bhe = Bh + wbase;
    const __nv_bfloat16* Ble = Bl + wbase;
    const float* bvec = bias + (long)e * N;

    const uint32_t sb = smem_u32(smem);
    const int tid  = threadIdx.x;
    const int wid  = tid >> 5;
    const int lane = tid & 31;
    const int wm   = wid & 3;      // 4 M-warps x 32 rows
    const int wn   = wid >> 2;     // 2 N-warps x 64 cols

    float acc[16][4];
#pragma unroll
    for (int i = 0; i < 16; i++)
#pragma unroll
        for (int j = 0; j < 4; j++) acc[i][j] = 0.f;

    const int lr = ((lane >> 3) & 1) * 8 + (lane & 7);
    const int lc = (lane >> 4) * 16;

    // precomputed loop-invariant ldsm offsets (within a stage)
    uint32_t offA[2][2], offB[2][4];
#pragma unroll
    for (int ks = 0; ks < 2; ks++) {
        const int kb = ks * 32 + lc;
#pragma unroll
        for (int mt = 0; mt < 2; mt++)
            offA[ks][mt] = sw64((uint32_t)((wm * 32 + mt * 16 + lr) * 64 + kb));
#pragma unroll
        for (int nt = 0; nt < 4; nt++)
            offB[ks][nt] = sw64((uint32_t)((wn * 64 + nt * 16 + lr) * 64 + kb));
    }

    const int nk = K / TK;

#define LOAD_CHUNK(kc_)                                                       \
    do {                                                                      \
        const uint32_t base_ = sb + ((kc_) % 3) * STG_SZ;                     \
        const int kbase_ = (kc_) * TK;                                        \
        _Pragma("unroll")                                                     \
        for (int i = 0; i < 4; i++) {                                         \
            int u    = tid + i * 256;                                         \
            int half = u >> 9;                                                \
            int v    = u & 511;                                               \
            int r    = v >> 2;                                                \
            int c    = v & 3;                                                 \
            int gm = m0 + r;                                                  \
            if (gm >= mend) gm = mend - 1;                                    \
            int src = rowmap ? rowmap[gm] : gm;                               \
            const __nv_bfloat16* g = (half ? Al : Ah) + (long)src * K + kbase_ + c * 8; \
            uint32_t d = base_ + (half ? O_AL : O_AH) + sw64((uint32_t)(r * 64 + c * 16)); \
            cpa16(d, g);                                                      \
        }                                                                     \
        _Pragma("unroll")                                                     \
        for (int i = 0; i < 4; i++) {                                         \
            int u    = tid + i * 256;                                         \
            int half = u >> 9;                                                \
            int v    = u & 511;                                               \
            int r    = v >> 2;                                                \
            int c    = v & 3;                                                 \
            const __nv_bfloat16* g = (half ? Ble : Bhe) + (long)(n0 + r) * K + kbase_ + c * 8; \
            uint32_t d = base_ + (half ? O_BL : O_BH) + sw64((uint32_t)(r * 64 + c * 16)); \
            cpa16(d, g);                                                      \
        }                                                                     \
        CP_COMMIT();                                                          \
    } while (0)

    LOAD_CHUNK(0);
    if (nk > 1) LOAD_CHUNK(1);

    for (int kc = 0; kc < nk; kc++) {
        if (kc == nk - 1) { CP_WAIT0(); } else { CP_WAIT1(); }
        __syncthreads();
        if (kc + 2 < nk) LOAD_CHUNK(kc + 2);

        const uint32_t base = sb + (kc % 3) * STG_SZ;
#pragma unroll
        for (int ks = 0; ks < 2; ks++) {
            uint32_t ahf[2][4], alf[2][4], bfrag[4][4];
#pragma unroll
            for (int mt = 0; mt < 2; mt++) {
                ldsm_x4(ahf[mt], base + O_AH + offA[ks][mt]);
                ldsm_x4(alf[mt], base + O_AL + offA[ks][mt]);
            }
#pragma unroll
            for (int nt = 0; nt < 4; nt++)
                ldsm_x4(bfrag[nt], base + O_BH + offB[ks][nt]);

            // pass 1: ah*bh — 16 distinct accumulators
#pragma unroll
            for (int mt = 0; mt < 2; mt++)
#pragma unroll
                for (int nt = 0; nt < 4; nt++) {
                    mma_bf16(acc[mt * 8 + nt * 2 + 0], ahf[mt], bfrag[nt][0], bfrag[nt][2]);
                    mma_bf16(acc[mt * 8 + nt * 2 + 1], ahf[mt], bfrag[nt][1], bfrag[nt][3]);
                }
            // pass 2: al*bh — 16 distinct accumulators
#pragma unroll
            for (int mt = 0; mt < 2; mt++)
#pragma unroll
                for (int nt = 0; nt < 4; nt++) {
                    mma_bf16(acc[mt * 8 + nt * 2 + 0], alf[mt], bfrag[nt][0], bfrag[nt][2]);
                    mma_bf16(acc[mt * 8 + nt * 2 + 1], alf[mt], bfrag[nt][1], bfrag[nt][3]);
                }
            // pass 3: ah*bl — 16 distinct accumulators
#pragma unroll
            for (int nt = 0; nt < 4; nt++)
                ldsm_x4(bfrag[nt], base + O_BL + offB[ks][nt]);
#pragma unroll
            for (int mt = 0; mt < 2; mt++)
#pragma unroll
                for (int nt = 0; nt < 4; nt++) {
                    mma_bf16(acc[mt * 8 + nt * 2 + 0], ahf[mt], bfrag[nt][0], bfrag[nt][2]);
                    mma_bf16(acc[mt * 8 + nt * 2 + 1], ahf[mt], bfrag[nt][1], bfrag[nt][3]);
                }
        }
    }
#undef LOAD_CHUNK

    // ---- epilogue: bias + relu, then either split bf16 hi/lo or fp32 store
#pragma unroll
    for (int mt = 0; mt < 2; mt++) {
#pragma unroll
        for (int nt = 0; nt < 8; nt++) {
            const float* a4 = acc[mt * 8 + nt];
            int col  = n0 + wn * 64 + nt * 8 + ((lane & 3) << 1);
            float bb0 = bvec[col], bb1 = bvec[col + 1];
            int row0 = m0 + wm * 32 + mt * 16 + (lane >> 2);
            int row1 = row0 + 8;
            float v0 = a4[0] + bb0, v1 = a4[1] + bb1;
            float v2 = a4[2] + bb0, v3 = a4[3] + bb1;
            if (relu) {
                v0 = fmaxf(v0, 0.f); v1 = fmaxf(v1, 0.f);
                v2 = fmaxf(v2, 0.f); v3 = fmaxf(v3, 0.f);
            }
            if (Cf) {
                if (row0 < mend)
                    *reinterpret_cast<float2*>(Cf + (long)row0 * N + col) = make_float2(v0, v1);
                if (row1 < mend)
                    *reinterpret_cast<float2*>(Cf + (long)row1 * N + col) = make_float2(v2, v3);
            } else {
                if (row0 < mend) {
                    __nv_bfloat162 h, l;
                    h.x = __float2bfloat16(v0); h.y = __float2bfloat16(v1);
                    l.x = __float2bfloat16(v0 - __bfloat162float(h.x));
                    l.y = __float2bfloat16(v1 - __bfloat162float(h.y));
                    *reinterpret_cast<uint32_t*>(Ch + (long)row0 * N + col) = *reinterpret_cast<uint32_t*>(&h);
                    *reinterpret_cast<uint32_t*>(Cl + (long)row0 * N + col) = *reinterpret_cast<uint32_t*>(&l);
                }
                if (row1 < mend) {
                    __nv_bfloat162 h, l;
                    h.x = __float2bfloat16(v2); h.y = __float2bfloat16(v3);
                    l.x = __float2bfloat16(v2 - __bfloat162float(h.x));
                    l.y = __float2bfloat16(v3 - __bfloat162float(h.y));
                    *reinterpret_cast<uint32_t*>(Ch + (long)row1 * N + col) = *reinterpret_cast<uint32_t*>(&h);
                    *reinterpret_cast<uint32_t*>(Cl + (long)row1 * N + col) = *reinterpret_cast<uint32_t*>(&l);
                }
            }
        }
    }
}

// ---------------- split / transpose pre-passes ------------------------------
__global__ __launch_bounds__(256) void k_splitx(const float* __restrict__ x)
{
    long i = (long)(blockIdx.x * 256 + threadIdx.x) * 4;
    if (i >= (long)BQ * DQ) return;
    float4 v = *reinterpret_cast<const float4*>(x + i);
    __nv_bfloat162 h0, l0, h1, l1;
    h0.x = __float2bfloat16(v.x); h0.y = __float2bfloat16(v.y);
    l0.x = __float2bfloat16(v.x - __bfloat162float(h0.x));
    l0.y = __float2bfloat16(v.y - __bfloat162float(h0.y));
    h1.x = __float2bfloat16(v.z); h1.y = __float2bfloat16(v.w);
    l1.x = __float2bfloat16(v.z - __bfloat162float(h1.x));
    l1.y = __float2bfloat16(v.w - __bfloat162float(h1.y));
    *reinterpret_cast<uint2*>(g_xh + i) = make_uint2(
        *reinterpret_cast<uint32_t*>(&h0), *reinterpret_cast<uint32_t*>(&h1));
    *reinterpret_cast<uint2*>(g_xl + i) = make_uint2(
        *reinterpret_cast<uint32_t*>(&l0), *reinterpret_cast<uint32_t*>(&l1));
}

// W [E][K][N] f32 -> Wh/Wl [E][N][K] bf16
__global__ __launch_bounds__(256) void k_splitw(
    const float* __restrict__ src, __nv_bfloat16* __restrict__ dh,
    __nv_bfloat16* __restrict__ dl, int K, int N)
{
    __shared__ float t[32][33];
    const int e  = blockIdx.z;
    const int n0 = blockIdx.x * 32;
    const int k0 = blockIdx.y * 32;
    const int tx = threadIdx.x & 31;
    const int ty = threadIdx.x >> 5;  // 0..7
    const float* S = src + (long)e * K * N;
    const long ob  = (long)e * N * K;
#pragma unroll
    for (int i = 0; i < 32; i += 8)
        t[ty + i][tx] = S[(long)(k0 + ty + i) * N + n0 + tx];
    __syncthreads();
#pragma unroll
    for (int i = 0; i < 32; i += 8) {
        float v = t[tx][ty + i];
        __nv_bfloat16 h = __float2bfloat16(v);
        __nv_bfloat16 l = __float2bfloat16(v - __bfloat162float(h));
        long o = ob + (long)(n0 + ty + i) * K + k0 + tx;
        dh[o] = h;
        dl[o] = l;
    }
}

// ---------------- fp32 SGEMM (gate layer 1 only) ---------------------------
__global__ __launch_bounds__(256) void sgemm_seg(
    const float* __restrict__ A,
    const float* __restrict__ Wbase,
    const float* __restrict__ bias,
    float* __restrict__ C,
    const int* __restrict__ seg_off,
    const int* __restrict__ seg_cnt,
    int K, int N, int relu)
{
    const int e    = blockIdx.z;
    const int mseg = seg_off[e];
    const int mend = mseg + seg_cnt[e];
    const int m0   = mseg + blockIdx.y * 128;
    if (m0 >= mend) return;
    const int n0 = blockIdx.x * 128;

    const float* W    = Wbase;
    const float* bvec = bias;

    __shared__ float Ast[16][128];
    __shared__ float Bs [16][128];

    const int tid = threadIdx.x;
    const int tx  = tid & 15;
    const int ty  = tid >> 4;

    float acc[8][8];
#pragma unroll
    for (int m = 0; m < 8; m++)
#pragma unroll
        for (int n = 0; n < 8; n++) acc[m][n] = 0.f;

    for (int k0 = 0; k0 < K; k0 += 16) {
#pragma unroll
        for (int i = 0; i < 2; i++) {
            int q  = tid + i * 256;
            int r  = q >> 2;
            int c4 = q & 3;
            int gm = m0 + r;
            float4 v = make_float4(0.f, 0.f, 0.f, 0.f);
            if (gm < mend)
                v = *reinterpret_cast<const float4*>(A + (long)gm * K + k0 + c4 * 4);
            Ast[c4 * 4 + 0][r] = v.x;
            Ast[c4 * 4 + 1][r] = v.y;
            Ast[c4 * 4 + 2][r] = v.z;
            Ast[c4 * 4 + 3][r] = v.w;
        }
#pragma unroll
        for (int i = 0; i < 2; i++) {
            int q  = tid + i * 256;
            int r  = q >> 5;
            int c4 = q & 31;
            float4 v = *reinterpret_cast<const float4*>(W + (long)(k0 + r) * N + n0 + c4 * 4);
            *reinterpret_cast<float4*>(&Bs[r][c4 * 4]) = v;
        }
        __syncthreads();

#pragma unroll
        for (int kk = 0; kk < 16; kk++) {
            float4 a0 = *reinterpret_cast<const float4*>(&Ast[kk][ty * 8]);
            float4 a1 = *reinterpret_cast<const float4*>(&Ast[kk][ty * 8 + 4]);
            float4 b0 = *reinterpret_cast<const float4*>(&Bs[kk][tx * 8]);
            float4 b1 = *reinterpret_cast<const float4*>(&Bs[kk][tx * 8 + 4]);
            float ra[8] = {a0.x, a0.y, a0.z, a0.w, a1.x, a1.y, a1.z, a1.w};
            float rb[8] = {b0.x, b0.y, b0.z, b0.w, b1.x, b1.y, b1.z, b1.w};
#pragma unroll
            for (int m = 0; m < 8; m++)
#pragma unroll
                for (int n = 0; n < 8; n++) acc[m][n] = fmaf(ra[m], rb[n], acc[m][n]);
        }
        __syncthreads();
    }

#pragma unroll
    for (int m = 0; m < 8; m++) {
        int gm = m0 + ty * 8 + m;
        if (gm >= mend) continue;
        float* crow = C + (long)gm * N;
#pragma unroll
        for (int n = 0; n < 8; n++) {
            int gn = n0 + tx * 8 + n;
            float v = acc[m][n] + bvec[gn];
            if (relu) v = fmaxf(v, 0.f);
            crow[gn] = v;
        }
    }
}

// ---------------- small kernels ------------------------------------------
__global__ void k_zero()
{
    int t = threadIdx.x;
    if (t < EQ) { g_cnt[t] = 0; g_cursor[t] = 0; }
}

__global__ __launch_bounds__(128) void k_gate2(const float* __restrict__ Wg2,
                                               const float* __restrict__ bg2)
{
    int b    = blockIdx.x * 4 + (threadIdx.x >> 5);
    int lane = threadIdx.x & 31;
    const float* grow = g_g + (long)b * GQ;

    float acc[8] = {0, 0, 0, 0, 0, 0, 0, 0};
    for (int k = lane; k < GQ; k += 32) {
        float gv = grow[k];
        const float* w = Wg2 + k * 8;
#pragma unroll
        for (int e = 0; e < 8; e++) acc[e] = fmaf(gv, w[e], acc[e]);
    }
#pragma unroll
    for (int e = 0; e < 8; e++) {
#pragma unroll
        for (int o = 16; o; o >>= 1) acc[e] += __shfl_xor_sync(0xffffffffu, acc[e], o);
    }
    if (lane == 0) {
        float l[8], m = -1e30f;
#pragma unroll
        for (int e = 0; e < 8; e++) { l[e] = acc[e] + bg2[e]; m = fmaxf(m, l[e]); }
        float s = 0.f;
#pragma unroll
        for (int e = 0; e < 8; e++) { l[e] = expf(l[e] - m); s += l[e]; }
        float inv = 1.f / s;
#pragma unroll
        for (int e = 0; e < 8; e++) { l[e] *= inv; g_gatew[b * 8 + e] = l[e]; }
        int i0 = 0;
#pragma unroll
        for (int e = 1; e < 8; e++) if (l[e] > l[i0]) i0 = e;
        int i1 = -1;
#pragma unroll
        for (int e = 0; e < 8; e++) {
            if (e == i0) continue;
            if (i1 < 0 || l[e] > l[i1]) i1 = e;
        }
        float w0 = l[i0], w1 = l[i1];
        float mm = fmaxf(w0, w1);
        float e0 = expf(w0 - mm), e1 = expf(w1 - mm);
        float si = 1.f / (e0 + e1);
        g_topidx[2 * b]     = i0;
        g_topidx[2 * b + 1] = i1;
        g_topw[2 * b]       = e0 * si;
        g_topw[2 * b + 1]   = e1 * si;
        atomicAdd(&g_cnt[i0], 1);
        atomicAdd(&g_cnt[i1], 1);
    }
}

__global__ void k_offsets()
{
    if (threadIdx.x == 0) {
        int s = 0;
        for (int e = 0; e < EQ; e++) { g_off[e] = s; s += g_cnt[e]; }
        g_off[EQ] = s;
    }
}

__global__ void k_scatter()
{
    int b = blockIdx.x * blockDim.x + threadIdx.x;
    if (b >= BQ) return;
#pragma unroll
    for (int s = 0; s < 2; s++) {
        int e = g_topidx[2 * b + s];
        int p = g_off[e] + atomicAdd(&g_cursor[e], 1);
        g_ptok[p]         = b;
        g_pidx[2 * b + s] = p;
    }
}

__global__ __launch_bounds__(256) void k_usage()
{
    int e = blockIdx.x, t = threadIdx.x;
    __shared__ float sh[256];
    float s = 0.f;
    for (int b = t; b < BQ; b += 256) s += g_gatew[b * 8 + e];
    sh[t] = s;
    __syncthreads();
    for (int o = 128; o; o >>= 1) {
        if (t < o) sh[t] += sh[t + o];
        __syncthreads();
    }
    if (t == 0) g_usage[e] = sh[0];
}

__global__ void k_loss(float* out, int out_size)
{
    if (threadIdx.x == 0 && out_size > BQ * DOUTQ) {
        float acc = 0.f;
        for (int e = 0; e < EQ; e++) {
            float d = g_usage[e] / (float)BQ - 1.0f / (float)EQ;
            acc += d * d;
        }
        out[BQ * DOUTQ] = acc / (float)EQ;
    }
}

__global__ __launch_bounds__(256) void k_combine(float* __restrict__ out)
{
    int b  = blockIdx.x;
    int p0 = g_pidx[2 * b], p1 = g_pidx[2 * b + 1];
    float w0 = g_topw[2 * b], w1 = g_topw[2 * b + 1];
    const float* y0 = g_y + (long)p0 * DOUTQ;
    const float* y1 = g_y + (long)p1 * DOUTQ;
    float* o = out + (long)b * DOUTQ;
    for (int d = threadIdx.x; d < DOUTQ; d += 256)
        o[d] = w0 * y0[d] + w1 * y1[d];
}

// ---------------- launch --------------------------------------------------
extern "C" void kernel_launch(void* const* d_in, const int* in_sizes, int n_in,
                              void* d_out, int out_size)
{
    const float* x   = (const float*)d_in[0];
    const float* W1  = (const float*)d_in[1];
    const float* b1  = (const float*)d_in[2];
    const float* W2  = (const float*)d_in[3];
    const float* b2  = (const float*)d_in[4];
    const float* W3  = (const float*)d_in[5];
    const float* b3  = (const float*)d_in[6];
    const float* Wg1 = (const float*)d_in[7];
    const float* bg1 = (const float*)d_in[8];
    const float* Wg2 = (const float*)d_in[9];
    const float* bg2 = (const float*)d_in[10];
    float* out = (float*)d_out;

    float* p_g;
    float* p_y;
    int *p_goff, *p_gcnt, *p_off, *p_cnt, *p_ptok;
    __nv_bfloat16 *p_xh, *p_xl, *p_w1h, *p_w1l, *p_w2h, *p_w2l, *p_w3h, *p_w3l;
    __nv_bfloat16 *p_h1h, *p_h1l, *p_h2h, *p_h2l;
    cudaGetSymbolAddress((void**)&p_g,    g_g);
    cudaGetSymbolAddress((void**)&p_y,    g_y);
    cudaGetSymbolAddress((void**)&p_goff, g_gate_off);
    cudaGetSymbolAddress((void**)&p_gcnt, g_gate_cnt);
    cudaGetSymbolAddress((void**)&p_off,  g_off);
    cudaGetSymbolAddress((void**)&p_cnt,  g_cnt);
    cudaGetSymbolAddress((void**)&p_ptok, g_ptok);
    cudaGetSymbolAddress((void**)&p_xh,   g_xh);
    cudaGetSymbolAddress((void**)&p_xl,   g_xl);
    cudaGetSymbolAddress((void**)&p_w1h,  g_w1h);
    cudaGetSymbolAddress((void**)&p_w1l,  g_w1l);
    cudaGetSymbolAddress((void**)&p_w2h,  g_w2h);
    cudaGetSymbolAddress((void**)&p_w2l,  g_w2l);
    cudaGetSymbolAddress((void**)&p_w3h,  g_w3h);
    cudaGetSymbolAddress((void**)&p_w3l,  g_w3l);
    cudaGetSymbolAddress((void**)&p_h1h,  g_h1h);
    cudaGetSymbolAddress((void**)&p_h1l,  g_h1l);
    cudaGetSymbolAddress((void**)&p_h2h,  g_h2h);
    cudaGetSymbolAddress((void**)&p_h2l,  g_h2l);

    cudaFuncSetAttribute(moe_bf16_gemm3,
                         cudaFuncAttributeMaxDynamicSharedMemorySize, SMEM_SZ);

    k_zero<<<1, 32>>>();

    // pre-split x and weights (hi/lo bf16, W transposed to [E][N][K])
    k_splitx<<<(BQ * DQ / 4 + 255) / 256, 256>>>(x);
    {
        dim3 g1(HQ / 32, DQ / 32, EQ);
        k_splitw<<<g1, 256>>>(W1, p_w1h, p_w1l, DQ, HQ);
        dim3 g2(H2Q / 32, HQ / 32, EQ);
        k_splitw<<<g2, 256>>>(W2, p_w2h, p_w2l, HQ, H2Q);
        dim3 g3(DOUTQ / 32, H2Q / 32, EQ);
        k_splitw<<<g3, 256>>>(W3, p_w3h, p_w3l, H2Q, DOUTQ);
    }

    // gate: g = relu(x @ Wg1 + bg1) then layer2 + softmax + top2 + routing
    {
        dim3 grid(GQ / 128, BQ / 128, 1);
        sgemm_seg<<<grid, 256>>>(x, Wg1, bg1, p_g, p_goff, p_gcnt, DQ, GQ, 1);
    }
    k_gate2<<<BQ / 4, 128>>>(Wg2, bg2);
    k_offsets<<<1, 32>>>();
    k_scatter<<<BQ / 256, 256>>>();
    k_usage<<<EQ, 256>>>();
    k_loss<<<1, 32>>>(out, out_size);

    // expert layer 1: h1 = relu(gather(x) @ W1[e] + b1[e])  K=1024, N=4096
    {
        dim3 grid(HQ / TN, PAIRS / TM, EQ);
        moe_bf16_gemm3<<<grid, 256, SMEM_SZ>>>(
            p_xh, p_xl, p_w1h, p_w1l, b1, p_h1h, p_h1l, nullptr,
            p_ptok, p_off, p_cnt, DQ, HQ, 1);
    }
    // expert layer 2: h2 = relu(h1 @ W2[e] + b2[e])  K=4096, N=2048
    {
        dim3 grid(H2Q / TN, PAIRS / TM, EQ);
        moe_bf16_gemm3<<<grid, 256, SMEM_SZ>>>(
            p_h1h, p_h1l, p_w2h, p_w2l, b2, p_h2h, p_h2l, nullptr,
            nullptr, p_off, p_cnt, HQ, H2Q, 1);
    }
    // expert layer 3: y = h2 @ W3[e] + b3[e]  K=2048, N=1024
    {
        dim3 grid(DOUTQ / TN, PAIRS / TM, EQ);
        moe_bf16_gemm3<<<grid, 256, SMEM_SZ>>>(
            p_h2h, p_h2l, p_w3h, p_w3l, b3, nullptr, nullptr, p_y,
            nullptr, p_off, p_cnt, H2Q, DOUTQ, 0);
    }
    k_combine<<<BQ, 256>>>(out);
}

// round 10
// speedup vs baseline: 1.4897x; 1.4897x over previous
#include <cuda_runtime.h>
#include <cuda_fp16.h>
#include <math.h>
#include <stdint.h>

// Problem constants
#define BQ    8192
#define DQ    1024
#define HQ    4096
#define H2Q   2048
#define DOUTQ 1024
#define EQ    8
#define GQ    512
#define PAIRS (BQ * 2)

// ---------------- scratch (device globals) ---------------------------------
__device__ float g_g[BQ * GQ];
__device__ float g_y [PAIRS * DOUTQ];
__device__ float g_gatew[BQ * EQ];
__device__ int   g_topidx[BQ * 2];
__device__ float g_topw [BQ * 2];
__device__ int   g_cnt[EQ];
__device__ int   g_off[EQ + 1];
__device__ int   g_cursor[EQ];
__device__ int   g_ptok[PAIRS];
__device__ int   g_pidx[BQ * 2];
__device__ float g_usage[EQ];
__device__ int   g_gate_off[1] = {0};
__device__ int   g_gate_cnt[1] = {BQ};

// fp16 operands: activations single, weights hi/lo pair
__device__ __half g_x  [BQ * DQ];
__device__ __half g_w1h[EQ * DQ * HQ];
__device__ __half g_w1l[EQ * DQ * HQ];
__device__ __half g_w2h[EQ * HQ * H2Q];
__device__ __half g_w2l[EQ * HQ * H2Q];
__device__ __half g_w3h[EQ * H2Q * DOUTQ];
__device__ __half g_w3l[EQ * H2Q * DOUTQ];
__device__ __half g_h1 [PAIRS * HQ];
__device__ __half g_h2 [PAIRS * H2Q];

// ---------------- helpers ---------------------------------------------------
__device__ __forceinline__ uint32_t smem_u32(const void* p) {
    uint32_t a;
    asm("{ .reg .u64 t; cvta.to.shared.u64 t, %1; cvt.u32.u64 %0, t; }"
        : "=r"(a) : "l"(p));
    return a;
}
__device__ __forceinline__ uint32_t sw64(uint32_t off) {
    return off ^ ((off >> 3) & 0x30);
}
__device__ __forceinline__ void ldsm_x4(uint32_t* r, uint32_t addr) {
    asm volatile("ldmatrix.sync.aligned.m8n8.x4.shared.b16 {%0,%1,%2,%3}, [%4];"
                 : "=r"(r[0]), "=r"(r[1]), "=r"(r[2]), "=r"(r[3]) : "r"(addr));
}
__device__ __forceinline__ void mma_f16(float* d, const uint32_t* a,
                                        uint32_t b0, uint32_t b1) {
    asm volatile(
        "mma.sync.aligned.m16n8k16.row.col.f32.f16.f16.f32 "
        "{%0,%1,%2,%3}, {%4,%5,%6,%7}, {%8,%9}, {%0,%1,%2,%3};"
        : "+f"(d[0]), "+f"(d[1]), "+f"(d[2]), "+f"(d[3])
        : "r"(a[0]), "r"(a[1]), "r"(a[2]), "r"(a[3]), "r"(b0), "r"(b1));
}
__device__ __forceinline__ void cpa16(uint32_t d, const void* s) {
    asm volatile("cp.async.cg.shared.global [%0], [%1], 16;" :: "r"(d), "l"(s));
}
#define CP_COMMIT() asm volatile("cp.async.commit_group;" ::: "memory")
#define CP_WAIT1()  asm volatile("cp.async.wait_group 1;" ::: "memory")
#define CP_WAIT0()  asm volatile("cp.async.wait_group 0;" ::: "memory")

// ---------------- 2xFP16 pipelined segmented GEMM ---------------------------
// C[gm, n0..n0+128) = act(A[row(gm),:] @ (Wh+Wl)_e^T + bias_e)
// A: fp16 [rows][K]; W: fp16 hi/lo [E][N][K] (pre-transposed).
// CTA tile 128Mx128N, K-chunk 32, 256 threads (4M x 2N warps), 3-stage cp.async,
// 2 CTAs/SM. smem rows 64B with SW64 swizzle. 2 MMAs per product: a*wh + a*wl.
#define TM 128
#define TN 128
#define TK 32
#define O_A    0                 // 128*32*2 = 8192 bytes
#define O_BH   8192
#define O_BL   16384
#define STG_SZ 24576
#define SMEM_SZ (3 * STG_SZ)     // 73728

__global__ __launch_bounds__(256, 2) void moe_f16_gemm(
    const __half* __restrict__ Ax,
    const __half* __restrict__ Bh, const __half* __restrict__ Bl,
    const float* __restrict__ bias,
    __half* __restrict__ Chf,
    float* __restrict__ Cf,
    const int* __restrict__ rowmap,
    const int* __restrict__ seg_off,
    const int* __restrict__ seg_cnt,
    int K, int N, int relu)
{
    extern __shared__ char smem[];
    const int e    = blockIdx.z;
    const int mseg = seg_off[e];
    const int mend = mseg + seg_cnt[e];
    const int m0   = mseg + blockIdx.y * TM;
    if (m0 >= mend) return;
    const int n0 = blockIdx.x * TN;

    const long wbase = (long)e * (long)N * (long)K;
    const __half* Bhe = Bh + wbase;
    const __half* Ble = Bl + wbase;
    const float* bvec = bias + (long)e * N;

    const uint32_t sb = smem_u32(smem);
    const int tid  = threadIdx.x;
    const int wid  = tid >> 5;
    const int lane = tid & 31;
    const int wm   = wid & 3;      // 4 M-warps x 32 rows
    const int wn   = wid >> 2;     // 2 N-warps x 64 cols

    float acc[16][4];
#pragma unroll
    for (int i = 0; i < 16; i++)
#pragma unroll
        for (int j = 0; j < 4; j++) acc[i][j] = 0.f;

    const int lr = ((lane >> 3) & 1) * 8 + (lane & 7);
    const int lc = (lane >> 4) * 16;

    // loop-invariant ldsm offsets (within a stage)
    uint32_t offA[2][2], offB[2][4];
#pragma unroll
    for (int ks = 0; ks < 2; ks++) {
        const int kb = ks * 32 + lc;
#pragma unroll
        for (int mt = 0; mt < 2; mt++)
            offA[ks][mt] = sw64((uint32_t)((wm * 32 + mt * 16 + lr) * 64 + kb));
#pragma unroll
        for (int nt = 0; nt < 4; nt++)
            offB[ks][nt] = sw64((uint32_t)((wn * 64 + nt * 16 + lr) * 64 + kb));
    }

    const int nk = K / TK;

#define LOAD_CHUNK(kc_)                                                       \
    do {                                                                      \
        const uint32_t base_ = sb + ((kc_) % 3) * STG_SZ;                     \
        const int kbase_ = (kc_) * TK;                                        \
        _Pragma("unroll")                                                     \
        for (int i = 0; i < 2; i++) {                                         \
            int u = tid + i * 256;        /* 512 16B chunks for A */          \
            int r = u >> 2;                                                   \
            int c = u & 3;                                                    \
            int gm = m0 + r;                                                  \
            if (gm >= mend) gm = mend - 1;                                    \
            int src = rowmap ? rowmap[gm] : gm;                               \
            const __half* g = Ax + (long)src * K + kbase_ + c * 8;            \
            uint32_t d = base_ + O_A + sw64((uint32_t)(r * 64 + c * 16));     \
            cpa16(d, g);                                                      \
        }                                                                     \
        _Pragma("unroll")                                                     \
        for (int i = 0; i < 4; i++) {     /* 1024 16B chunks for B hi+lo */   \
            int u    = tid + i * 256;                                         \
            int half_ = u >> 9;                                               \
            int v    = u & 511;                                               \
            int r    = v >> 2;                                                \
            int c    = v & 3;                                                 \
            const __half* g = (half_ ? Ble : Bhe) + (long)(n0 + r) * K + kbase_ + c * 8; \
            uint32_t d = base_ + (half_ ? O_BL : O_BH) + sw64((uint32_t)(r * 64 + c * 16)); \
            cpa16(d, g);                                                      \
        }                                                                     \
        CP_COMMIT();                                                          \
    } while (0)

    LOAD_CHUNK(0);
    if (nk > 1) LOAD_CHUNK(1);

    for (int kc = 0; kc < nk; kc++) {
        if (kc == nk - 1) { CP_WAIT0(); } else { CP_WAIT1(); }
        __syncthreads();
        if (kc + 2 < nk) LOAD_CHUNK(kc + 2);

        const uint32_t base = sb + (kc % 3) * STG_SZ;
#pragma unroll
        for (int ks = 0; ks < 2; ks++) {
            uint32_t af[2][4], bfrag[4][4];
#pragma unroll
            for (int mt = 0; mt < 2; mt++)
                ldsm_x4(af[mt], base + O_A + offA[ks][mt]);
#pragma unroll
            for (int nt = 0; nt < 4; nt++)
                ldsm_x4(bfrag[nt], base + O_BH + offB[ks][nt]);

            // pass 1: a*wh — 16 distinct accumulators
#pragma unroll
            for (int mt = 0; mt < 2; mt++)
#pragma unroll
                for (int nt = 0; nt < 4; nt++) {
                    mma_f16(acc[mt * 8 + nt * 2 + 0], af[mt], bfrag[nt][0], bfrag[nt][2]);
                    mma_f16(acc[mt * 8 + nt * 2 + 1], af[mt], bfrag[nt][1], bfrag[nt][3]);
                }
            // pass 2: a*wl — 16 distinct accumulators
#pragma unroll
            for (int nt = 0; nt < 4; nt++)
                ldsm_x4(bfrag[nt], base + O_BL + offB[ks][nt]);
#pragma unroll
            for (int mt = 0; mt < 2; mt++)
#pragma unroll
                for (int nt = 0; nt < 4; nt++) {
                    mma_f16(acc[mt * 8 + nt * 2 + 0], af[mt], bfrag[nt][0], bfrag[nt][2]);
                    mma_f16(acc[mt * 8 + nt * 2 + 1], af[mt], bfrag[nt][1], bfrag[nt][3]);
                }
        }
    }
#undef LOAD_CHUNK

    // ---- epilogue: bias + relu, then fp16 store (h) or fp32 store (y)
#pragma unroll
    for (int mt = 0; mt < 2; mt++) {
#pragma unroll
        for (int nt = 0; nt < 8; nt++) {
            const float* a4 = acc[mt * 8 + nt];
            int col  = n0 + wn * 64 + nt * 8 + ((lane & 3) << 1);
            float bb0 = bvec[col], bb1 = bvec[col + 1];
            int row0 = m0 + wm * 32 + mt * 16 + (lane >> 2);
            int row1 = row0 + 8;
            float v0 = a4[0] + bb0, v1 = a4[1] + bb1;
            float v2 = a4[2] + bb0, v3 = a4[3] + bb1;
            if (relu) {
                v0 = fmaxf(v0, 0.f); v1 = fmaxf(v1, 0.f);
                v2 = fmaxf(v2, 0.f); v3 = fmaxf(v3, 0.f);
            }
            if (Cf) {
                if (row0 < mend)
                    *reinterpret_cast<float2*>(Cf + (long)row0 * N + col) = make_float2(v0, v1);
                if (row1 < mend)
                    *reinterpret_cast<float2*>(Cf + (long)row1 * N + col) = make_float2(v2, v3);
            } else {
                if (row0 < mend) {
                    __half2 h;
                    h.x = __float2half_rn(v0); h.y = __float2half_rn(v1);
                    *reinterpret_cast<uint32_t*>(Chf + (long)row0 * N + col) =
                        *reinterpret_cast<uint32_t*>(&h);
                }
                if (row1 < mend) {
                    __half2 h;
                    h.x = __float2half_rn(v2); h.y = __float2half_rn(v3);
                    *reinterpret_cast<uint32_t*>(Chf + (long)row1 * N + col) =
                        *reinterpret_cast<uint32_t*>(&h);
                }
            }
        }
    }
}

// ---------------- split / transpose pre-passes ------------------------------
__global__ __launch_bounds__(256) void k_splitx(const float* __restrict__ x)
{
    long i = (long)(blockIdx.x * 256 + threadIdx.x) * 4;
    if (i >= (long)BQ * DQ) return;
    float4 v = *reinterpret_cast<const float4*>(x + i);
    __half2 h0, h1;
    h0.x = __float2half_rn(v.x); h0.y = __float2half_rn(v.y);
    h1.x = __float2half_rn(v.z); h1.y = __float2half_rn(v.w);
    *reinterpret_cast<uint2*>(g_x + i) = make_uint2(
        *reinterpret_cast<uint32_t*>(&h0), *reinterpret_cast<uint32_t*>(&h1));
}

// W [E][K][N] f32 -> Wh/Wl [E][N][K] fp16
__global__ __launch_bounds__(256) void k_splitw(
    const float* __restrict__ src, __half* __restrict__ dh,
    __half* __restrict__ dl, int K, int N)
{
    __shared__ float t[32][33];
    const int e  = blockIdx.z;
    const int n0 = blockIdx.x * 32;
    const int k0 = blockIdx.y * 32;
    const int tx = threadIdx.x & 31;
    const int ty = threadIdx.x >> 5;  // 0..7
    const float* S = src + (long)e * K * N;
    const long ob  = (long)e * N * K;
#pragma unroll
    for (int i = 0; i < 32; i += 8)
        t[ty + i][tx] = S[(long)(k0 + ty + i) * N + n0 + tx];
    __syncthreads();
#pragma unroll
    for (int i = 0; i < 32; i += 8) {
        float v = t[tx][ty + i];
        __half h = __float2half_rn(v);
        __half l = __float2half_rn(v - __half2float(h));
        long o = ob + (long)(n0 + ty + i) * K + k0 + tx;
        dh[o] = h;
        dl[o] = l;
    }
}

// ---------------- fp32 SGEMM (gate layer 1 only) ---------------------------
__global__ __launch_bounds__(256) void sgemm_seg(
    const float* __restrict__ A,
    const float* __restrict__ Wbase,
    const float* __restrict__ bias,
    float* __restrict__ C,
    const int* __restrict__ seg_off,
    const int* __restrict__ seg_cnt,
    int K, int N, int relu)
{
    const int e    = blockIdx.z;
    const int mseg = seg_off[e];
    const int mend = mseg + seg_cnt[e];
    const int m0   = mseg + blockIdx.y * 128;
    if (m0 >= mend) return;
    const int n0 = blockIdx.x * 128;

    const float* W    = Wbase;
    const float* bvec = bias;

    __shared__ float Ast[16][128];
    __shared__ float Bs [16][128];

    const int tid = threadIdx.x;
    const int tx  = tid & 15;
    const int ty  = tid >> 4;

    float acc[8][8];
#pragma unroll
    for (int m = 0; m < 8; m++)
#pragma unroll
        for (int n = 0; n < 8; n++) acc[m][n] = 0.f;

    for (int k0 = 0; k0 < K; k0 += 16) {
#pragma unroll
        for (int i = 0; i < 2; i++) {
            int q  = tid + i * 256;
            int r  = q >> 2;
            int c4 = q & 3;
            int gm = m0 + r;
            float4 v = make_float4(0.f, 0.f, 0.f, 0.f);
            if (gm < mend)
                v = *reinterpret_cast<const float4*>(A + (long)gm * K + k0 + c4 * 4);
            Ast[c4 * 4 + 0][r] = v.x;
            Ast[c4 * 4 + 1][r] = v.y;
            Ast[c4 * 4 + 2][r] = v.z;
            Ast[c4 * 4 + 3][r] = v.w;
        }
#pragma unroll
        for (int i = 0; i < 2; i++) {
            int q  = tid + i * 256;
            int r  = q >> 5;
            int c4 = q & 31;
            float4 v = *reinterpret_cast<const float4*>(W + (long)(k0 + r) * N + n0 + c4 * 4);
            *reinterpret_cast<float4*>(&Bs[r][c4 * 4]) = v;
        }
        __syncthreads();

#pragma unroll
        for (int kk = 0; kk < 16; kk++) {
            float4 a0 = *reinterpret_cast<const float4*>(&Ast[kk][ty * 8]);
            float4 a1 = *reinterpret_cast<const float4*>(&Ast[kk][ty * 8 + 4]);
            float4 b0 = *reinterpret_cast<const float4*>(&Bs[kk][tx * 8]);
            float4 b1 = *reinterpret_cast<const float4*>(&Bs[kk][tx * 8 + 4]);
            float ra[8] = {a0.x, a0.y, a0.z, a0.w, a1.x, a1.y, a1.z, a1.w};
            float rb[8] = {b0.x, b0.y, b0.z, b0.w, b1.x, b1.y, b1.z, b1.w};
#pragma unroll
            for (int m = 0; m < 8; m++)
#pragma unroll
                for (int n = 0; n < 8; n++) acc[m][n] = fmaf(ra[m], rb[n], acc[m][n]);
        }
        __syncthreads();
    }

#pragma unroll
    for (int m = 0; m < 8; m++) {
        int gm = m0 + ty * 8 + m;
        if (gm >= mend) continue;
        float* crow = C + (long)gm * N;
#pragma unroll
        for (int n = 0; n < 8; n++) {
            int gn = n0 + tx * 8 + n;
            float v = acc[m][n] + bvec[gn];
            if (relu) v = fmaxf(v, 0.f);
            crow[gn] = v;
        }
    }
}

// ---------------- small kernels ------------------------------------------
__global__ void k_zero()
{
    int t = threadIdx.x;
    if (t < EQ) { g_cnt[t] = 0; g_cursor[t] = 0; }
}

__global__ __launch_bounds__(128) void k_gate2(const float* __restrict__ Wg2,
                                               const float* __restrict__ bg2)
{
    int b    = blockIdx.x * 4 + (threadIdx.x >> 5);
    int lane = threadIdx.x & 31;
    const float* grow = g_g + (long)b * GQ;

    float acc[8] = {0, 0, 0, 0, 0, 0, 0, 0};
    for (int k = lane; k < GQ; k += 32) {
        float gv = grow[k];
        const float* w = Wg2 + k * 8;
#pragma unroll
        for (int e = 0; e < 8; e++) acc[e] = fmaf(gv, w[e], acc[e]);
    }
#pragma unroll
    for (int e = 0; e < 8; e++) {
#pragma unroll
        for (int o = 16; o; o >>= 1) acc[e] += __shfl_xor_sync(0xffffffffu, acc[e], o);
    }
    if (lane == 0) {
        float l[8], m = -1e30f;
#pragma unroll
        for (int e = 0; e < 8; e++) { l[e] = acc[e] + bg2[e]; m = fmaxf(m, l[e]); }
        float s = 0.f;
#pragma unroll
        for (int e = 0; e < 8; e++) { l[e] = expf(l[e] - m); s += l[e]; }
        float inv = 1.f / s;
#pragma unroll
        for (int e = 0; e < 8; e++) { l[e] *= inv; g_gatew[b * 8 + e] = l[e]; }
        int i0 = 0;
#pragma unroll
        for (int e = 1; e < 8; e++) if (l[e] > l[i0]) i0 = e;
        int i1 = -1;
#pragma unroll
        for (int e = 0; e < 8; e++) {
            if (e == i0) continue;
            if (i1 < 0 || l[e] > l[i1]) i1 = e;
        }
        float w0 = l[i0], w1 = l[i1];
        float mm = fmaxf(w0, w1);
        float e0 = expf(w0 - mm), e1 = expf(w1 - mm);
        float si = 1.f / (e0 + e1);
        g_topidx[2 * b]     = i0;
        g_topidx[2 * b + 1] = i1;
        g_topw[2 * b]       = e0 * si;
        g_topw[2 * b + 1]   = e1 * si;
        atomicAdd(&g_cnt[i0], 1);
        atomicAdd(&g_cnt[i1], 1);
    }
}

__global__ void k_offsets()
{
    if (threadIdx.x == 0) {
        int s = 0;
        for (int e = 0; e < EQ; e++) { g_off[e] = s; s += g_cnt[e]; }
        g_off[EQ] = s;
    }
}

__global__ void k_scatter()
{
    int b = blockIdx.x * blockDim.x + threadIdx.x;
    if (b >= BQ) return;
#pragma unroll
    for (int s = 0; s < 2; s++) {
        int e = g_topidx[2 * b + s];
        int p = g_off[e] + atomicAdd(&g_cursor[e], 1);
        g_ptok[p]         = b;
        g_pidx[2 * b + s] = p;
    }
}

__global__ __launch_bounds__(256) void k_usage()
{
    int e = blockIdx.x, t = threadIdx.x;
    __shared__ float sh[256];
    float s = 0.f;
    for (int b = t; b < BQ; b += 256) s += g_gatew[b * 8 + e];
    sh[t] = s;
    __syncthreads();
    for (int o = 128; o; o >>= 1) {
        if (t < o) sh[t] += sh[t + o];
        __syncthreads();
    }
    if (t == 0) g_usage[e] = sh[0];
}

__global__ void k_loss(float* out, int out_size)
{
    if (threadIdx.x == 0 && out_size > BQ * DOUTQ) {
        float acc = 0.f;
        for (int e = 0; e < EQ; e++) {
            float d = g_usage[e] / (float)BQ - 1.0f / (float)EQ;
            acc += d * d;
        }
        out[BQ * DOUTQ] = acc / (float)EQ;
    }
}

__global__ __launch_bounds__(256) void k_combine(float* __restrict__ out)
{
    int b  = blockIdx.x;
    int p0 = g_pidx[2 * b], p1 = g_pidx[2 * b + 1];
    float w0 = g_topw[2 * b], w1 = g_topw[2 * b + 1];
    const float* y0 = g_y + (long)p0 * DOUTQ;
    const float* y1 = g_y + (long)p1 * DOUTQ;
    float* o = out + (long)b * DOUTQ;
    for (int d = threadIdx.x; d < DOUTQ; d += 256)
        o[d] = w0 * y0[d] + w1 * y1[d];
}

// ---------------- launch --------------------------------------------------
extern "C" void kernel_launch(void* const* d_in, const int* in_sizes, int n_in,
                              void* d_out, int out_size)
{
    const float* x   = (const float*)d_in[0];
    const float* W1  = (const float*)d_in[1];
    const float* b1  = (const float*)d_in[2];
    const float* W2  = (const float*)d_in[3];
    const float* b2  = (const float*)d_in[4];
    const float* W3  = (const float*)d_in[5];
    const float* b3  = (const float*)d_in[6];
    const float* Wg1 = (const float*)d_in[7];
    const float* bg1 = (const float*)d_in[8];
    const float* Wg2 = (const float*)d_in[9];
    const float* bg2 = (const float*)d_in[10];
    float* out = (float*)d_out;

    float* p_g;
    float* p_y;
    int *p_goff, *p_gcnt, *p_off, *p_cnt, *p_ptok;
    __half *p_x, *p_w1h, *p_w1l, *p_w2h, *p_w2l, *p_w3h, *p_w3l, *p_h1, *p_h2;
    cudaGetSymbolAddress((void**)&p_g,    g_g);
    cudaGetSymbolAddress((void**)&p_y,    g_y);
    cudaGetSymbolAddress((void**)&p_goff, g_gate_off);
    cudaGetSymbolAddress((void**)&p_gcnt, g_gate_cnt);
    cudaGetSymbolAddress((void**)&p_off,  g_off);
    cudaGetSymbolAddress((void**)&p_cnt,  g_cnt);
    cudaGetSymbolAddress((void**)&p_ptok, g_ptok);
    cudaGetSymbolAddress((void**)&p_x,    g_x);
    cudaGetSymbolAddress((void**)&p_w1h,  g_w1h);
    cudaGetSymbolAddress((void**)&p_w1l,  g_w1l);
    cudaGetSymbolAddress((void**)&p_w2h,  g_w2h);
    cudaGetSymbolAddress((void**)&p_w2l,  g_w2l);
    cudaGetSymbolAddress((void**)&p_w3h,  g_w3h);
    cudaGetSymbolAddress((void**)&p_w3l,  g_w3l);
    cudaGetSymbolAddress((void**)&p_h1,   g_h1);
    cudaGetSymbolAddress((void**)&p_h2,   g_h2);

    cudaFuncSetAttribute(moe_f16_gemm,
                         cudaFuncAttributeMaxDynamicSharedMemorySize, SMEM_SZ);

    k_zero<<<1, 32>>>();

    // pre-split x (fp16) and weights (fp16 hi/lo, transposed to [E][N][K])
    k_splitx<<<(BQ * DQ / 4 + 255) / 256, 256>>>(x);
    {
        dim3 g1(HQ / 32, DQ / 32, EQ);
        k_splitw<<<g1, 256>>>(W1, p_w1h, p_w1l, DQ, HQ);
        dim3 g2(H2Q / 32, HQ / 32, EQ);
        k_splitw<<<g2, 256>>>(W2, p_w2h, p_w2l, HQ, H2Q);
        dim3 g3(DOUTQ / 32, H2Q / 32, EQ);
        k_splitw<<<g3, 256>>>(W3, p_w3h, p_w3l, H2Q, DOUTQ);
    }

    // gate: g = relu(x @ Wg1 + bg1) then layer2 + softmax + top2 + routing
    {
        dim3 grid(GQ / 128, BQ / 128, 1);
        sgemm_seg<<<grid, 256>>>(x, Wg1, bg1, p_g, p_goff, p_gcnt, DQ, GQ, 1);
    }
    k_gate2<<<BQ / 4, 128>>>(Wg2, bg2);
    k_offsets<<<1, 32>>>();
    k_scatter<<<BQ / 256, 256>>>();
    k_usage<<<EQ, 256>>>();
    k_loss<<<1, 32>>>(out, out_size);

    // expert layer 1: h1 = relu(gather(x) @ W1[e] + b1[e])  K=1024, N=4096
    {
        dim3 grid(HQ / TN, PAIRS / TM, EQ);
        moe_f16_gemm<<<grid, 256, SMEM_SZ>>>(
            p_x, p_w1h, p_w1l, b1, p_h1, nullptr,
            p_ptok, p_off, p_cnt, DQ, HQ, 1);
    }
    // expert layer 2: h2 = relu(h1 @ W2[e] + b2[e])  K=4096, N=2048
    {
        dim3 grid(H2Q / TN, PAIRS / TM, EQ);
        moe_f16_gemm<<<grid, 256, SMEM_SZ>>>(
            p_h1, p_w2h, p_w2l, b2, p_h2, nullptr,
            nullptr, p_off, p_cnt, HQ, H2Q, 1);
    }
    // expert layer 3: y = h2 @ W3[e] + b3[e]  K=2048, N=1024
    {
        dim3 grid(DOUTQ / TN, PAIRS / TM, EQ);
        moe_f16_gemm<<<grid, 256, SMEM_SZ>>>(
            p_h2, p_w3h, p_w3l, b3, nullptr, p_y,
            nullptr, p_off, p_cnt, H2Q, DOUTQ, 0);
    }
    k_combine<<<BQ, 256>>>(out);
}

// round 11
// speedup vs baseline: 2.0293x; 1.3623x over previous
#include <cuda_runtime.h>
#include <cuda_fp16.h>
#include <math.h>
#include <stdint.h>

// Problem constants
#define BQ    8192
#define DQ    1024
#define HQ    4096
#define H2Q   2048
#define DOUTQ 1024
#define EQ    8
#define GQ    512
#define PAIRS (BQ * 2)
#define MAXTILES (PAIRS / 128 + EQ)   // 136

// ---------------- scratch (device globals) ---------------------------------
__device__ float g_g[BQ * GQ];
__device__ float g_y [PAIRS * DOUTQ];
__device__ float g_gatew[BQ * EQ];
__device__ int   g_topidx[BQ * 2];
__device__ float g_topw [BQ * 2];
__device__ int   g_cnt[EQ];
__device__ int   g_off[EQ + 1];
__device__ int   g_cursor[EQ];
__device__ int   g_ptok[PAIRS];
__device__ int   g_pidx[BQ * 2];
__device__ float g_usage[EQ];
__device__ int   g_gate_off[1] = {0};
__device__ int   g_gate_cnt[1] = {BQ};
__device__ int   g_tiles[MAXTILES];
__device__ int   g_ntiles;

// fp16 operands
__device__ __half g_x  [BQ * DQ];
__device__ __half g_w1h[EQ * DQ * HQ];
__device__ __half g_w1l[EQ * DQ * HQ];
__device__ __half g_w2h[EQ * HQ * H2Q];
__device__ __half g_w3h[EQ * H2Q * DOUTQ];
__device__ __half g_h1 [PAIRS * HQ];
__device__ __half g_h2 [PAIRS * H2Q];

// ---------------- helpers ---------------------------------------------------
__device__ __forceinline__ uint32_t smem_u32(const void* p) {
    uint32_t a;
    asm("{ .reg .u64 t; cvta.to.shared.u64 t, %1; cvt.u32.u64 %0, t; }"
        : "=r"(a) : "l"(p));
    return a;
}
__device__ __forceinline__ uint32_t sw64(uint32_t off) {
    return off ^ ((off >> 3) & 0x30);
}
__device__ __forceinline__ void ldsm_x4(uint32_t* r, uint32_t addr) {
    asm volatile("ldmatrix.sync.aligned.m8n8.x4.shared.b16 {%0,%1,%2,%3}, [%4];"
                 : "=r"(r[0]), "=r"(r[1]), "=r"(r[2]), "=r"(r[3]) : "r"(addr));
}
__device__ __forceinline__ void mma_f16(float* d, const uint32_t* a,
                                        uint32_t b0, uint32_t b1) {
    asm volatile(
        "mma.sync.aligned.m16n8k16.row.col.f32.f16.f16.f32 "
        "{%0,%1,%2,%3}, {%4,%5,%6,%7}, {%8,%9}, {%0,%1,%2,%3};"
        : "+f"(d[0]), "+f"(d[1]), "+f"(d[2]), "+f"(d[3])
        : "r"(a[0]), "r"(a[1]), "r"(a[2]), "r"(a[3]), "r"(b0), "r"(b1));
}
__device__ __forceinline__ void cpa16(uint32_t d, const void* s) {
    asm volatile("cp.async.cg.shared.global [%0], [%1], 16;" :: "r"(d), "l"(s));
}
#define CP_COMMIT() asm volatile("cp.async.commit_group;" ::: "memory")
#define CP_WAIT1()  asm volatile("cp.async.wait_group 1;" ::: "memory")
#define CP_WAIT0()  asm volatile("cp.async.wait_group 0;" ::: "memory")

// ---------------- fp16 pipelined segmented GEMM -----------------------------
// C[gm, n0..n0+128) = act(A[row(gm),:] @ (Wh[+Wl])_e^T + bias_e)
// Tile list in g_tiles (device-built). CTA tile 128x128, K-chunk 32,
// 256 threads (4M x 2N warps), 3-stage cp.async, 2 CTAs/SM, SW64 64B rows.
#define TM 128
#define TN 128
#define TK 32
#define O_A    0                 // 8192 bytes
#define O_BH   8192
#define O_BL   16384
#define STG_SZ 24576
#define SMEM_SZ (3 * STG_SZ)     // 73728

__global__ __launch_bounds__(256, 2) void moe_f16_gemm(
    const __half* __restrict__ Ax,
    const __half* __restrict__ Bh, const __half* __restrict__ Bl,
    const float* __restrict__ bias,
    __half* __restrict__ Chf,
    float* __restrict__ Cf,
    const int* __restrict__ rowmap,
    int K, int N, int relu, int two_term)
{
    extern __shared__ char smem[];
    if ((int)blockIdx.y >= g_ntiles) return;
    const int d    = g_tiles[blockIdx.y];
    const int e    = d & 255;
    const int ts   = d >> 8;
    const int mseg = g_off[e];
    const int mend = mseg + g_cnt[e];
    const int m0   = mseg + ts * TM;
    const int n0   = blockIdx.x * TN;

    const long wbase = (long)e * (long)N * (long)K;
    const __half* Bhe = Bh + wbase;
    const __half* Ble = two_term ? (Bl + wbase) : Bhe;
    const float* bvec = bias + (long)e * N;

    const uint32_t sb = smem_u32(smem);
    const int tid  = threadIdx.x;
    const int wid  = tid >> 5;
    const int lane = tid & 31;
    const int wm   = wid & 3;      // 4 M-warps x 32 rows
    const int wn   = wid >> 2;     // 2 N-warps x 64 cols

    float acc[16][4];
#pragma unroll
    for (int i = 0; i < 16; i++)
#pragma unroll
        for (int j = 0; j < 4; j++) acc[i][j] = 0.f;

    const int lr = ((lane >> 3) & 1) * 8 + (lane & 7);
    const int lc = (lane >> 4) * 16;

    uint32_t offA[2][2], offB[2][4];
#pragma unroll
    for (int ks = 0; ks < 2; ks++) {
        const int kb = ks * 32 + lc;
#pragma unroll
        for (int mt = 0; mt < 2; mt++)
            offA[ks][mt] = sw64((uint32_t)((wm * 32 + mt * 16 + lr) * 64 + kb));
#pragma unroll
        for (int nt = 0; nt < 4; nt++)
            offB[ks][nt] = sw64((uint32_t)((wn * 64 + nt * 16 + lr) * 64 + kb));
    }

    const int nk = K / TK;

#define LOAD_CHUNK(kc_)                                                       \
    do {                                                                      \
        const uint32_t base_ = sb + ((kc_) % 3) * STG_SZ;                     \
        const int kbase_ = (kc_) * TK;                                        \
        _Pragma("unroll")                                                     \
        for (int i = 0; i < 2; i++) {        /* A: 512 16B chunks */          \
            int u = tid + i * 256;                                            \
            int r = u >> 2;                                                   \
            int c = u & 3;                                                    \
            int gm = m0 + r;                                                  \
            if (gm >= mend) gm = mend - 1;                                    \
            int src = rowmap ? rowmap[gm] : gm;                               \
            const __half* g = Ax + (long)src * K + kbase_ + c * 8;            \
            uint32_t dd = base_ + O_A + sw64((uint32_t)(r * 64 + c * 16));    \
            cpa16(dd, g);                                                     \
        }                                                                     \
        _Pragma("unroll")                                                     \
        for (int i = 0; i < 4; i++) {        /* B hi (+lo): 16B chunks */     \
            if (i >= 2 && !two_term) break;                                   \
            int u     = tid + i * 256;                                        \
            int half_ = u >> 9;                                               \
            int v     = u & 511;                                              \
            int r     = v >> 2;                                               \
            int c     = v & 3;                                                \
            const __half* g = (half_ ? Ble : Bhe) + (long)(n0 + r) * K + kbase_ + c * 8; \
            uint32_t dd = base_ + (half_ ? O_BL : O_BH) + sw64((uint32_t)(r * 64 + c * 16)); \
            cpa16(dd, g);                                                     \
        }                                                                     \
        CP_COMMIT();                                                          \
    } while (0)

    LOAD_CHUNK(0);
    if (nk > 1) LOAD_CHUNK(1);

    for (int kc = 0; kc < nk; kc++) {
        if (kc == nk - 1) { CP_WAIT0(); } else { CP_WAIT1(); }
        __syncthreads();
        if (kc + 2 < nk) LOAD_CHUNK(kc + 2);

        const uint32_t base = sb + (kc % 3) * STG_SZ;
#pragma unroll
        for (int ks = 0; ks < 2; ks++) {
            uint32_t af[2][4], bfrag[4][4];
#pragma unroll
            for (int mt = 0; mt < 2; mt++)
                ldsm_x4(af[mt], base + O_A + offA[ks][mt]);
#pragma unroll
            for (int nt = 0; nt < 4; nt++)
                ldsm_x4(bfrag[nt], base + O_BH + offB[ks][nt]);

            // pass 1: a*wh — 16 distinct accumulators
#pragma unroll
            for (int mt = 0; mt < 2; mt++)
#pragma unroll
                for (int nt = 0; nt < 4; nt++) {
                    mma_f16(acc[mt * 8 + nt * 2 + 0], af[mt], bfrag[nt][0], bfrag[nt][2]);
                    mma_f16(acc[mt * 8 + nt * 2 + 1], af[mt], bfrag[nt][1], bfrag[nt][3]);
                }
            // pass 2: a*wl (two-term layers only)
            if (two_term) {
#pragma unroll
                for (int nt = 0; nt < 4; nt++)
                    ldsm_x4(bfrag[nt], base + O_BL + offB[ks][nt]);
#pragma unroll
                for (int mt = 0; mt < 2; mt++)
#pragma unroll
                    for (int nt = 0; nt < 4; nt++) {
                        mma_f16(acc[mt * 8 + nt * 2 + 0], af[mt], bfrag[nt][0], bfrag[nt][2]);
                        mma_f16(acc[mt * 8 + nt * 2 + 1], af[mt], bfrag[nt][1], bfrag[nt][3]);
                    }
            }
        }
    }
#undef LOAD_CHUNK

    // ---- epilogue
#pragma unroll
    for (int mt = 0; mt < 2; mt++) {
#pragma unroll
        for (int nt = 0; nt < 8; nt++) {
            const float* a4 = acc[mt * 8 + nt];
            int col  = n0 + wn * 64 + nt * 8 + ((lane & 3) << 1);
            float bb0 = bvec[col], bb1 = bvec[col + 1];
            int row0 = m0 + wm * 32 + mt * 16 + (lane >> 2);
            int row1 = row0 + 8;
            float v0 = a4[0] + bb0, v1 = a4[1] + bb1;
            float v2 = a4[2] + bb0, v3 = a4[3] + bb1;
            if (relu) {
                v0 = fmaxf(v0, 0.f); v1 = fmaxf(v1, 0.f);
                v2 = fmaxf(v2, 0.f); v3 = fmaxf(v3, 0.f);
            }
            if (Cf) {
                if (row0 < mend)
                    *reinterpret_cast<float2*>(Cf + (long)row0 * N + col) = make_float2(v0, v1);
                if (row1 < mend)
                    *reinterpret_cast<float2*>(Cf + (long)row1 * N + col) = make_float2(v2, v3);
            } else {
                if (row0 < mend) {
                    __half2 h;
                    h.x = __float2half_rn(v0); h.y = __float2half_rn(v1);
                    *reinterpret_cast<uint32_t*>(Chf + (long)row0 * N + col) =
                        *reinterpret_cast<uint32_t*>(&h);
                }
                if (row1 < mend) {
                    __half2 h;
                    h.x = __float2half_rn(v2); h.y = __float2half_rn(v3);
                    *reinterpret_cast<uint32_t*>(Chf + (long)row1 * N + col) =
                        *reinterpret_cast<uint32_t*>(&h);
                }
            }
        }
    }
}

// ---------------- split / transpose pre-passes ------------------------------
__global__ __launch_bounds__(256) void k_splitx(const float* __restrict__ x)
{
    long i = (long)(blockIdx.x * 256 + threadIdx.x) * 4;
    if (i >= (long)BQ * DQ) return;
    float4 v = *reinterpret_cast<const float4*>(x + i);
    __half2 h0, h1;
    h0.x = __float2half_rn(v.x); h0.y = __float2half_rn(v.y);
    h1.x = __float2half_rn(v.z); h1.y = __float2half_rn(v.w);
    *reinterpret_cast<uint2*>(g_x + i) = make_uint2(
        *reinterpret_cast<uint32_t*>(&h0), *reinterpret_cast<uint32_t*>(&h1));
}

// W [E][K][N] f32 -> Wh (+Wl) [E][N][K] fp16, vectorized
__global__ __launch_bounds__(256) void k_splitw(
    const float* __restrict__ src, __half* __restrict__ dh,
    __half* __restrict__ dl, int K, int N)
{
    __shared__ float t[32][33];
    const int e  = blockIdx.z;
    const int n0 = blockIdx.x * 32;
    const int k0 = blockIdx.y * 32;
    const int tid = threadIdx.x;
    const float* S = src + (long)e * K * N;
    const long ob  = (long)e * N * K;
    {
        int kr = tid >> 3, n4 = tid & 7;
        float4 v = *reinterpret_cast<const float4*>(S + (long)(k0 + kr) * N + n0 + n4 * 4);
        t[kr][n4 * 4 + 0] = v.x;
        t[kr][n4 * 4 + 1] = v.y;
        t[kr][n4 * 4 + 2] = v.z;
        t[kr][n4 * 4 + 3] = v.w;
    }
    __syncthreads();
    {
        int n = tid >> 3, kq = tid & 7;
        float v0 = t[kq * 4 + 0][n], v1 = t[kq * 4 + 1][n];
        float v2 = t[kq * 4 + 2][n], v3 = t[kq * 4 + 3][n];
        __half2 h0, h1;
        h0.x = __float2half_rn(v0); h0.y = __float2half_rn(v1);
        h1.x = __float2half_rn(v2); h1.y = __float2half_rn(v3);
        long o = ob + (long)(n0 + n) * K + k0 + kq * 4;
        *reinterpret_cast<uint2*>(dh + o) = make_uint2(
            *reinterpret_cast<uint32_t*>(&h0), *reinterpret_cast<uint32_t*>(&h1));
        if (dl) {
            __half2 l0, l1;
            l0.x = __float2half_rn(v0 - __half2float(h0.x));
            l0.y = __float2half_rn(v1 - __half2float(h0.y));
            l1.x = __float2half_rn(v2 - __half2float(h1.x));
            l1.y = __float2half_rn(v3 - __half2float(h1.y));
            *reinterpret_cast<uint2*>(dl + o) = make_uint2(
                *reinterpret_cast<uint32_t*>(&l0), *reinterpret_cast<uint32_t*>(&l1));
        }
    }
}

// ---------------- fp32 SGEMM (gate layer 1 only) ---------------------------
__global__ __launch_bounds__(256) void sgemm_seg(
    const float* __restrict__ A,
    const float* __restrict__ Wbase,
    const float* __restrict__ bias,
    float* __restrict__ C,
    const int* __restrict__ seg_off,
    const int* __restrict__ seg_cnt,
    int K, int N, int relu)
{
    const int mseg = seg_off[0];
    const int mend = mseg + seg_cnt[0];
    const int m0   = mseg + blockIdx.y * 128;
    if (m0 >= mend) return;
    const int n0 = blockIdx.x * 128;

    const float* W    = Wbase;
    const float* bvec = bias;

    __shared__ float Ast[16][128];
    __shared__ float Bs [16][128];

    const int tid = threadIdx.x;
    const int tx  = tid & 15;
    const int ty  = tid >> 4;

    float acc[8][8];
#pragma unroll
    for (int m = 0; m < 8; m++)
#pragma unroll
        for (int n = 0; n < 8; n++) acc[m][n] = 0.f;

    for (int k0 = 0; k0 < K; k0 += 16) {
#pragma unroll
        for (int i = 0; i < 2; i++) {
            int q  = tid + i * 256;
            int r  = q >> 2;
            int c4 = q & 3;
            int gm = m0 + r;
            float4 v = make_float4(0.f, 0.f, 0.f, 0.f);
            if (gm < mend)
                v = *reinterpret_cast<const float4*>(A + (long)gm * K + k0 + c4 * 4);
            Ast[c4 * 4 + 0][r] = v.x;
            Ast[c4 * 4 + 1][r] = v.y;
            Ast[c4 * 4 + 2][r] = v.z;
            Ast[c4 * 4 + 3][r] = v.w;
        }
#pragma unroll
        for (int i = 0; i < 2; i++) {
            int q  = tid + i * 256;
            int r  = q >> 5;
            int c4 = q & 31;
            float4 v = *reinterpret_cast<const float4*>(W + (long)(k0 + r) * N + n0 + c4 * 4);
            *reinterpret_cast<float4*>(&Bs[r][c4 * 4]) = v;
        }
        __syncthreads();

#pragma unroll
        for (int kk = 0; kk < 16; kk++) {
            float4 a0 = *reinterpret_cast<const float4*>(&Ast[kk][ty * 8]);
            float4 a1 = *reinterpret_cast<const float4*>(&Ast[kk][ty * 8 + 4]);
            float4 b0 = *reinterpret_cast<const float4*>(&Bs[kk][tx * 8]);
            float4 b1 = *reinterpret_cast<const float4*>(&Bs[kk][tx * 8 + 4]);
            float ra[8] = {a0.x, a0.y, a0.z, a0.w, a1.x, a1.y, a1.z, a1.w};
            float rb[8] = {b0.x, b0.y, b0.z, b0.w, b1.x, b1.y, b1.z, b1.w};
#pragma unroll
            for (int m = 0; m < 8; m++)
#pragma unroll
                for (int n = 0; n < 8; n++) acc[m][n] = fmaf(ra[m], rb[n], acc[m][n]);
        }
        __syncthreads();
    }

#pragma unroll
    for (int m = 0; m < 8; m++) {
        int gm = m0 + ty * 8 + m;
        if (gm >= mend) continue;
        float* crow = C + (long)gm * N;
#pragma unroll
        for (int n = 0; n < 8; n++) {
            int gn = n0 + tx * 8 + n;
            float v = acc[m][n] + bvec[gn];
            if (relu) v = fmaxf(v, 0.f);
            crow[gn] = v;
        }
    }
}

// ---------------- small kernels ------------------------------------------
__global__ void k_zero()
{
    int t = threadIdx.x;
    if (t < EQ) { g_cnt[t] = 0; g_cursor[t] = 0; }
}

__global__ __launch_bounds__(128) void k_gate2(const float* __restrict__ Wg2,
                                               const float* __restrict__ bg2)
{
    int b    = blockIdx.x * 4 + (threadIdx.x >> 5);
    int lane = threadIdx.x & 31;
    const float* grow = g_g + (long)b * GQ;

    float acc[8] = {0, 0, 0, 0, 0, 0, 0, 0};
    for (int k = lane; k < GQ; k += 32) {
        float gv = grow[k];
        const float* w = Wg2 + k * 8;
#pragma unroll
        for (int e = 0; e < 8; e++) acc[e] = fmaf(gv, w[e], acc[e]);
    }
#pragma unroll
    for (int e = 0; e < 8; e++) {
#pragma unroll
        for (int o = 16; o; o >>= 1) acc[e] += __shfl_xor_sync(0xffffffffu, acc[e], o);
    }
    if (lane == 0) {
        float l[8], m = -1e30f;
#pragma unroll
        for (int e = 0; e < 8; e++) { l[e] = acc[e] + bg2[e]; m = fmaxf(m, l[e]); }
        float s = 0.f;
#pragma unroll
        for (int e = 0; e < 8; e++) { l[e] = expf(l[e] - m); s += l[e]; }
        float inv = 1.f / s;
#pragma unroll
        for (int e = 0; e < 8; e++) { l[e] *= inv; g_gatew[b * 8 + e] = l[e]; }
        int i0 = 0;
#pragma unroll
        for (int e = 1; e < 8; e++) if (l[e] > l[i0]) i0 = e;
        int i1 = -1;
#pragma unroll
        for (int e = 0; e < 8; e++) {
            if (e == i0) continue;
            if (i1 < 0 || l[e] > l[i1]) i1 = e;
        }
        float w0 = l[i0], w1 = l[i1];
        float mm = fmaxf(w0, w1);
        float e0 = expf(w0 - mm), e1 = expf(w1 - mm);
        float si = 1.f / (e0 + e1);
        g_topidx[2 * b]     = i0;
        g_topidx[2 * b + 1] = i1;
        g_topw[2 * b]       = e0 * si;
        g_topw[2 * b + 1]   = e1 * si;
        atomicAdd(&g_cnt[i0], 1);
        atomicAdd(&g_cnt[i1], 1);
    }
}

__global__ void k_offsets()
{
    if (threadIdx.x == 0) {
        int s = 0, idx = 0;
        for (int e = 0; e < EQ; e++) {
            g_off[e] = s;
            int c = g_cnt[e];
            s += c;
            int nt = (c + TM - 1) / TM;
            for (int t = 0; t < nt; t++) g_tiles[idx++] = e | (t << 8);
        }
        g_off[EQ] = s;
        g_ntiles = idx;
    }
}

__global__ void k_scatter()
{
    int b = blockIdx.x * blockDim.x + threadIdx.x;
    if (b >= BQ) return;
#pragma unroll
    for (int s = 0; s < 2; s++) {
        int e = g_topidx[2 * b + s];
        int p = g_off[e] + atomicAdd(&g_cursor[e], 1);
        g_ptok[p]         = b;
        g_pidx[2 * b + s] = p;
    }
}

__global__ __launch_bounds__(256) void k_usage()
{
    int e = blockIdx.x, t = threadIdx.x;
    __shared__ float sh[256];
    float s = 0.f;
    for (int b = t; b < BQ; b += 256) s += g_gatew[b * 8 + e];
    sh[t] = s;
    __syncthreads();
    for (int o = 128; o; o >>= 1) {
        if (t < o) sh[t] += sh[t + o];
        __syncthreads();
    }
    if (t == 0) g_usage[e] = sh[0];
}

__global__ void k_loss(float* out, int out_size)
{
    if (threadIdx.x == 0 && out_size > BQ * DOUTQ) {
        float acc = 0.f;
        for (int e = 0; e < EQ; e++) {
            float d = g_usage[e] / (float)BQ - 1.0f / (float)EQ;
            acc += d * d;
        }
        out[BQ * DOUTQ] = acc / (float)EQ;
    }
}

__global__ __launch_bounds__(256) void k_combine(float* __restrict__ out)
{
    int b  = blockIdx.x;
    int p0 = g_pidx[2 * b], p1 = g_pidx[2 * b + 1];
    float w0 = g_topw[2 * b], w1 = g_topw[2 * b + 1];
    const float* y0 = g_y + (long)p0 * DOUTQ;
    const float* y1 = g_y + (long)p1 * DOUTQ;
    float* o = out + (long)b * DOUTQ;
    for (int d = threadIdx.x; d < DOUTQ; d += 256)
        o[d] = w0 * y0[d] + w1 * y1[d];
}

// ---------------- launch --------------------------------------------------
extern "C" void kernel_launch(void* const* d_in, const int* in_sizes, int n_in,
                              void* d_out, int out_size)
{
    const float* x   = (const float*)d_in[0];
    const float* W1  = (const float*)d_in[1];
    const float* b1  = (const float*)d_in[2];
    const float* W2  = (const float*)d_in[3];
    const float* b2  = (const float*)d_in[4];
    const float* W3  = (const float*)d_in[5];
    const float* b3  = (const float*)d_in[6];
    const float* Wg1 = (const float*)d_in[7];
    const float* bg1 = (const float*)d_in[8];
    const float* Wg2 = (const float*)d_in[9];
    const float* bg2 = (const float*)d_in[10];
    float* out = (float*)d_out;

    float *p_g, *p_y;
    int *p_goff, *p_gcnt, *p_ptok;
    __half *p_x, *p_w1h, *p_w1l, *p_w2h, *p_w3h, *p_h1, *p_h2;
    cudaGetSymbolAddress((void**)&p_g,    g_g);
    cudaGetSymbolAddress((void**)&p_y,    g_y);
    cudaGetSymbolAddress((void**)&p_goff, g_gate_off);
    cudaGetSymbolAddress((void**)&p_gcnt, g_gate_cnt);
    cudaGetSymbolAddress((void**)&p_ptok, g_ptok);
    cudaGetSymbolAddress((void**)&p_x,    g_x);
    cudaGetSymbolAddress((void**)&p_w1h,  g_w1h);
    cudaGetSymbolAddress((void**)&p_w1l,  g_w1l);
    cudaGetSymbolAddress((void**)&p_w2h,  g_w2h);
    cudaGetSymbolAddress((void**)&p_w3h,  g_w3h);
    cudaGetSymbolAddress((void**)&p_h1,   g_h1);
    cudaGetSymbolAddress((void**)&p_h2,   g_h2);

    cudaFuncSetAttribute(moe_f16_gemm,
                         cudaFuncAttributeMaxDynamicSharedMemorySize, SMEM_SZ);

    k_zero<<<1, 32>>>();

    // pre-split x (fp16) and weights (W1: hi/lo pair, W2/W3: hi only)
    k_splitx<<<(BQ * DQ / 4 + 255) / 256, 256>>>(x);
    {
        dim3 g1(HQ / 32, DQ / 32, EQ);
        k_splitw<<<g1, 256>>>(W1, p_w1h, p_w1l, DQ, HQ);
        dim3 g2(H2Q / 32, HQ / 32, EQ);
        k_splitw<<<g2, 256>>>(W2, p_w2h, nullptr, HQ, H2Q);
        dim3 g3(DOUTQ / 32, H2Q / 32, EQ);
        k_splitw<<<g3, 256>>>(W3, p_w3h, nullptr, H2Q, DOUTQ);
    }

    // gate: g = relu(x @ Wg1 + bg1) then layer2 + softmax + top2 + routing
    {
        dim3 grid(GQ / 128, BQ / 128, 1);
        sgemm_seg<<<grid, 256>>>(x, Wg1, bg1, p_g, p_goff, p_gcnt, DQ, GQ, 1);
    }
    k_gate2<<<BQ / 4, 128>>>(Wg2, bg2);
    k_offsets<<<1, 32>>>();
    k_scatter<<<BQ / 256, 256>>>();
    k_usage<<<EQ, 256>>>();
    k_loss<<<1, 32>>>(out, out_size);

    // expert layer 1: h1 = relu(gather(x) @ (W1h+W1l)[e] + b1[e])  two-term
    {
        dim3 grid(HQ / TN, MAXTILES, 1);
        moe_f16_gemm<<<grid, 256, SMEM_SZ>>>(
            p_x, p_w1h, p_w1l, b1, p_h1, nullptr, p_ptok, DQ, HQ, 1, 1);
    }
    // expert layer 2: h2 = relu(h1 @ W2h[e] + b2[e])  single-term
    {
        dim3 grid(H2Q / TN, MAXTILES, 1);
        moe_f16_gemm<<<grid, 256, SMEM_SZ>>>(
            p_h1, p_w2h, nullptr, b2, p_h2, nullptr, nullptr, HQ, H2Q, 1, 0);
    }
    // expert layer 3: y = h2 @ W3h[e] + b3[e]  single-term
    {
        dim3 grid(DOUTQ / TN, MAXTILES, 1);
        moe_f16_gemm<<<grid, 256, SMEM_SZ>>>(
            p_h2, p_w3h, nullptr, b3, nullptr, p_y, nullptr, H2Q, DOUTQ, 0, 0);
    }
    k_combine<<<BQ, 256>>>(out);
}

// round 12
// speedup vs baseline: 2.3006x; 1.1337x over previous
#include <cuda_runtime.h>
#include <cuda_fp16.h>
#include <math.h>
#include <stdint.h>

// Problem constants
#define BQ    8192
#define DQ    1024
#define HQ    4096
#define H2Q   2048
#define DOUTQ 1024
#define EQ    8
#define GQ    512
#define PAIRS (BQ * 2)
#define MAXTILES (PAIRS / 128 + EQ)   // 136

// ---------------- scratch (device globals) ---------------------------------
__device__ float g_g[BQ * GQ];
__device__ float g_y [PAIRS * DOUTQ];
__device__ float g_gatew[BQ * EQ];
__device__ int   g_topidx[BQ * 2];
__device__ float g_topw [BQ * 2];
__device__ int   g_cnt[EQ];
__device__ int   g_off[EQ + 1];
__device__ int   g_cursor[EQ];
__device__ int   g_ptok[PAIRS];
__device__ int   g_pidx[BQ * 2];
__device__ float g_usage[EQ];
__device__ int   g_gate_off[1] = {0};
__device__ int   g_gate_cnt[1] = {BQ};
__device__ int   g_tiles[MAXTILES];
__device__ int   g_ntiles;

// fp16 operands (single precision term everywhere)
__device__ __half g_x  [BQ * DQ];
__device__ __half g_w1h[EQ * DQ * HQ];
__device__ __half g_w2h[EQ * HQ * H2Q];
__device__ __half g_w3h[EQ * H2Q * DOUTQ];
__device__ __half g_h1 [PAIRS * HQ];
__device__ __half g_h2 [PAIRS * H2Q];

// ---------------- helpers ---------------------------------------------------
__device__ __forceinline__ uint32_t smem_u32(const void* p) {
    uint32_t a;
    asm("{ .reg .u64 t; cvta.to.shared.u64 t, %1; cvt.u32.u64 %0, t; }"
        : "=r"(a) : "l"(p));
    return a;
}
__device__ __forceinline__ uint32_t sw64(uint32_t off) {
    return off ^ ((off >> 3) & 0x30);
}
__device__ __forceinline__ void ldsm_x4(uint32_t* r, uint32_t addr) {
    asm volatile("ldmatrix.sync.aligned.m8n8.x4.shared.b16 {%0,%1,%2,%3}, [%4];"
                 : "=r"(r[0]), "=r"(r[1]), "=r"(r[2]), "=r"(r[3]) : "r"(addr));
}
__device__ __forceinline__ void mma_f16(float* d, const uint32_t* a,
                                        uint32_t b0, uint32_t b1) {
    asm volatile(
        "mma.sync.aligned.m16n8k16.row.col.f32.f16.f16.f32 "
        "{%0,%1,%2,%3}, {%4,%5,%6,%7}, {%8,%9}, {%0,%1,%2,%3};"
        : "+f"(d[0]), "+f"(d[1]), "+f"(d[2]), "+f"(d[3])
        : "r"(a[0]), "r"(a[1]), "r"(a[2]), "r"(a[3]), "r"(b0), "r"(b1));
}
__device__ __forceinline__ void cpa16(uint32_t d, const void* s) {
    asm volatile("cp.async.cg.shared.global [%0], [%1], 16;" :: "r"(d), "l"(s));
}
#define CP_COMMIT() asm volatile("cp.async.commit_group;" ::: "memory")
#define CP_WAIT1()  asm volatile("cp.async.wait_group 1;" ::: "memory")
#define CP_WAIT0()  asm volatile("cp.async.wait_group 0;" ::: "memory")

// ---------------- fp16 pipelined segmented GEMM -----------------------------
// C[gm, n0..n0+128) = act(A[row(gm),:] @ Wh_e^T + bias_e)
// Tile list in g_tiles (device-built). CTA tile 128x128, K-chunk 32,
// 256 threads (4M x 2N warps), 3-stage cp.async, 2 CTAs/SM, SW64 64B rows.
#define TM 128
#define TN 128
#define TK 32
#define O_A    0                 // 8192 bytes
#define O_BH   8192
#define STG_SZ 16384
#define SMEM_SZ (3 * STG_SZ)     // 49152

__global__ __launch_bounds__(256, 2) void moe_f16_gemm(
    const __half* __restrict__ Ax,
    const __half* __restrict__ Bh,
    const float* __restrict__ bias,
    __half* __restrict__ Chf,
    float* __restrict__ Cf,
    const int* __restrict__ rowmap,
    int K, int N, int relu)
{
    extern __shared__ char smem[];
    if ((int)blockIdx.y >= g_ntiles) return;
    const int d    = g_tiles[blockIdx.y];
    const int e    = d & 255;
    const int ts   = d >> 8;
    const int mseg = g_off[e];
    const int mend = mseg + g_cnt[e];
    const int m0   = mseg + ts * TM;
    const int n0   = blockIdx.x * TN;

    const __half* Bhe = Bh + (long)e * (long)N * (long)K;
    const float* bvec = bias + (long)e * N;

    const uint32_t sb = smem_u32(smem);
    const int tid  = threadIdx.x;
    const int wid  = tid >> 5;
    const int lane = tid & 31;
    const int wm   = wid & 3;      // 4 M-warps x 32 rows
    const int wn   = wid >> 2;     // 2 N-warps x 64 cols

    float acc[16][4];
#pragma unroll
    for (int i = 0; i < 16; i++)
#pragma unroll
        for (int j = 0; j < 4; j++) acc[i][j] = 0.f;

    const int lr = ((lane >> 3) & 1) * 8 + (lane & 7);
    const int lc = (lane >> 4) * 16;

    uint32_t offA[2][2], offB[2][4];
#pragma unroll
    for (int ks = 0; ks < 2; ks++) {
        const int kb = ks * 32 + lc;
#pragma unroll
        for (int mt = 0; mt < 2; mt++)
            offA[ks][mt] = sw64((uint32_t)((wm * 32 + mt * 16 + lr) * 64 + kb));
#pragma unroll
        for (int nt = 0; nt < 4; nt++)
            offB[ks][nt] = sw64((uint32_t)((wn * 64 + nt * 16 + lr) * 64 + kb));
    }

    const int nk = K / TK;

#define LOAD_CHUNK(kc_)                                                       \
    do {                                                                      \
        const uint32_t base_ = sb + ((kc_) % 3) * STG_SZ;                     \
        const int kbase_ = (kc_) * TK;                                        \
        _Pragma("unroll")                                                     \
        for (int i = 0; i < 2; i++) {        /* A: 512 16B chunks */          \
            int u = tid + i * 256;                                            \
            int r = u >> 2;                                                   \
            int c = u & 3;                                                    \
            int gm = m0 + r;                                                  \
            if (gm >= mend) gm = mend - 1;                                    \
            int src = rowmap ? rowmap[gm] : gm;                               \
            const __half* g = Ax + (long)src * K + kbase_ + c * 8;            \
            uint32_t dd = base_ + O_A + sw64((uint32_t)(r * 64 + c * 16));    \
            cpa16(dd, g);                                                     \
        }                                                                     \
        _Pragma("unroll")                                                     \
        for (int i = 0; i < 2; i++) {        /* B: 512 16B chunks */          \
            int u = tid + i * 256;                                            \
            int r = u >> 2;                                                   \
            int c = u & 3;                                                    \
            const __half* g = Bhe + (long)(n0 + r) * K + kbase_ + c * 8;      \
            uint32_t dd = base_ + O_BH + sw64((uint32_t)(r * 64 + c * 16));   \
            cpa16(dd, g);                                                     \
        }                                                                     \
        CP_COMMIT();                                                          \
    } while (0)

    LOAD_CHUNK(0);
    if (nk > 1) LOAD_CHUNK(1);

    for (int kc = 0; kc < nk; kc++) {
        if (kc == nk - 1) { CP_WAIT0(); } else { CP_WAIT1(); }
        __syncthreads();
        if (kc + 2 < nk) LOAD_CHUNK(kc + 2);

        const uint32_t base = sb + (kc % 3) * STG_SZ;
#pragma unroll
        for (int ks = 0; ks < 2; ks++) {
            uint32_t af[2][4], bfrag[4][4];
#pragma unroll
            for (int mt = 0; mt < 2; mt++)
                ldsm_x4(af[mt], base + O_A + offA[ks][mt]);
#pragma unroll
            for (int nt = 0; nt < 4; nt++)
                ldsm_x4(bfrag[nt], base + O_BH + offB[ks][nt]);
#pragma unroll
            for (int mt = 0; mt < 2; mt++)
#pragma unroll
                for (int nt = 0; nt < 4; nt++) {
                    mma_f16(acc[mt * 8 + nt * 2 + 0], af[mt], bfrag[nt][0], bfrag[nt][2]);
                    mma_f16(acc[mt * 8 + nt * 2 + 1], af[mt], bfrag[nt][1], bfrag[nt][3]);
                }
        }
    }
#undef LOAD_CHUNK

    // ---- epilogue
#pragma unroll
    for (int mt = 0; mt < 2; mt++) {
#pragma unroll
        for (int nt = 0; nt < 8; nt++) {
            const float* a4 = acc[mt * 8 + nt];
            int col  = n0 + wn * 64 + nt * 8 + ((lane & 3) << 1);
            float bb0 = bvec[col], bb1 = bvec[col + 1];
            int row0 = m0 + wm * 32 + mt * 16 + (lane >> 2);
            int row1 = row0 + 8;
            float v0 = a4[0] + bb0, v1 = a4[1] + bb1;
            float v2 = a4[2] + bb0, v3 = a4[3] + bb1;
            if (relu) {
                v0 = fmaxf(v0, 0.f); v1 = fmaxf(v1, 0.f);
                v2 = fmaxf(v2, 0.f); v3 = fmaxf(v3, 0.f);
            }
            if (Cf) {
                if (row0 < mend)
                    *reinterpret_cast<float2*>(Cf + (long)row0 * N + col) = make_float2(v0, v1);
                if (row1 < mend)
                    *reinterpret_cast<float2*>(Cf + (long)row1 * N + col) = make_float2(v2, v3);
            } else {
                if (row0 < mend) {
                    __half2 h;
                    h.x = __float2half_rn(v0); h.y = __float2half_rn(v1);
                    *reinterpret_cast<uint32_t*>(Chf + (long)row0 * N + col) =
                        *reinterpret_cast<uint32_t*>(&h);
                }
                if (row1 < mend) {
                    __half2 h;
                    h.x = __float2half_rn(v2); h.y = __float2half_rn(v3);
                    *reinterpret_cast<uint32_t*>(Chf + (long)row1 * N + col) =
                        *reinterpret_cast<uint32_t*>(&h);
                }
            }
        }
    }
}

// ---------------- split / transpose pre-passes ------------------------------
__global__ __launch_bounds__(256) void k_splitx(const float* __restrict__ x)
{
    long i = (long)(blockIdx.x * 256 + threadIdx.x) * 4;
    if (i >= (long)BQ * DQ) return;
    float4 v = *reinterpret_cast<const float4*>(x + i);
    __half2 h0, h1;
    h0.x = __float2half_rn(v.x); h0.y = __float2half_rn(v.y);
    h1.x = __float2half_rn(v.z); h1.y = __float2half_rn(v.w);
    *reinterpret_cast<uint2*>(g_x + i) = make_uint2(
        *reinterpret_cast<uint32_t*>(&h0), *reinterpret_cast<uint32_t*>(&h1));
}

// W [E][K][N] f32 -> Wh [E][N][K] fp16, vectorized transpose+convert
__global__ __launch_bounds__(256) void k_splitw(
    const float* __restrict__ src, __half* __restrict__ dh, int K, int N)
{
    __shared__ float t[32][33];
    const int e  = blockIdx.z;
    const int n0 = blockIdx.x * 32;
    const int k0 = blockIdx.y * 32;
    const int tid = threadIdx.x;
    const float* S = src + (long)e * K * N;
    const long ob  = (long)e * N * K;
    {
        int kr = tid >> 3, n4 = tid & 7;
        float4 v = *reinterpret_cast<const float4*>(S + (long)(k0 + kr) * N + n0 + n4 * 4);
        t[kr][n4 * 4 + 0] = v.x;
        t[kr][n4 * 4 + 1] = v.y;
        t[kr][n4 * 4 + 2] = v.z;
        t[kr][n4 * 4 + 3] = v.w;
    }
    __syncthreads();
    {
        int n = tid >> 3, kq = tid & 7;
        float v0 = t[kq * 4 + 0][n], v1 = t[kq * 4 + 1][n];
        float v2 = t[kq * 4 + 2][n], v3 = t[kq * 4 + 3][n];
        __half2 h0, h1;
        h0.x = __float2half_rn(v0); h0.y = __float2half_rn(v1);
        h1.x = __float2half_rn(v2); h1.y = __float2half_rn(v3);
        long o = ob + (long)(n0 + n) * K + k0 + kq * 4;
        *reinterpret_cast<uint2*>(dh + o) = make_uint2(
            *reinterpret_cast<uint32_t*>(&h0), *reinterpret_cast<uint32_t*>(&h1));
    }
}

// ---------------- fp32 SGEMM (gate layer 1 only) ---------------------------
__global__ __launch_bounds__(256) void sgemm_seg(
    const float* __restrict__ A,
    const float* __restrict__ Wbase,
    const float* __restrict__ bias,
    float* __restrict__ C,
    const int* __restrict__ seg_off,
    const int* __restrict__ seg_cnt,
    int K, int N, int relu)
{
    const int mseg = seg_off[0];
    const int mend = mseg + seg_cnt[0];
    const int m0   = mseg + blockIdx.y * 128;
    if (m0 >= mend) return;
    const int n0 = blockIdx.x * 128;

    const float* W    = Wbase;
    const float* bvec = bias;

    __shared__ float Ast[16][128];
    __shared__ float Bs [16][128];

    const int tid = threadIdx.x;
    const int tx  = tid & 15;
    const int ty  = tid >> 4;

    float acc[8][8];
#pragma unroll
    for (int m = 0; m < 8; m++)
#pragma unroll
        for (int n = 0; n < 8; n++) acc[m][n] = 0.f;

    for (int k0 = 0; k0 < K; k0 += 16) {
#pragma unroll
        for (int i = 0; i < 2; i++) {
            int q  = tid + i * 256;
            int r  = q >> 2;
            int c4 = q & 3;
            int gm = m0 + r;
            float4 v = make_float4(0.f, 0.f, 0.f, 0.f);
            if (gm < mend)
                v = *reinterpret_cast<const float4*>(A + (long)gm * K + k0 + c4 * 4);
            Ast[c4 * 4 + 0][r] = v.x;
            Ast[c4 * 4 + 1][r] = v.y;
            Ast[c4 * 4 + 2][r] = v.z;
            Ast[c4 * 4 + 3][r] = v.w;
        }
#pragma unroll
        for (int i = 0; i < 2; i++) {
            int q  = tid + i * 256;
            int r  = q >> 5;
            int c4 = q & 31;
            float4 v = *reinterpret_cast<const float4*>(W + (long)(k0 + r) * N + n0 + c4 * 4);
            *reinterpret_cast<float4*>(&Bs[r][c4 * 4]) = v;
        }
        __syncthreads();

#pragma unroll
        for (int kk = 0; kk < 16; kk++) {
            float4 a0 = *reinterpret_cast<const float4*>(&Ast[kk][ty * 8]);
            float4 a1 = *reinterpret_cast<const float4*>(&Ast[kk][ty * 8 + 4]);
            float4 b0 = *reinterpret_cast<const float4*>(&Bs[kk][tx * 8]);
            float4 b1 = *reinterpret_cast<const float4*>(&Bs[kk][tx * 8 + 4]);
            float ra[8] = {a0.x, a0.y, a0.z, a0.w, a1.x, a1.y, a1.z, a1.w};
            float rb[8] = {b0.x, b0.y, b0.z, b0.w, b1.x, b1.y, b1.z, b1.w};
#pragma unroll
            for (int m = 0; m < 8; m++)
#pragma unroll
                for (int n = 0; n < 8; n++) acc[m][n] = fmaf(ra[m], rb[n], acc[m][n]);
        }
        __syncthreads();
    }

#pragma unroll
    for (int m = 0; m < 8; m++) {
        int gm = m0 + ty * 8 + m;
        if (gm >= mend) continue;
        float* crow = C + (long)gm * N;
#pragma unroll
        for (int n = 0; n < 8; n++) {
            int gn = n0 + tx * 8 + n;
            float v = acc[m][n] + bvec[gn];
            if (relu) v = fmaxf(v, 0.f);
            crow[gn] = v;
        }
    }
}

// ---------------- small kernels ------------------------------------------
__global__ void k_zero()
{
    int t = threadIdx.x;
    if (t < EQ) { g_cnt[t] = 0; g_cursor[t] = 0; }
}

__global__ __launch_bounds__(128) void k_gate2(const float* __restrict__ Wg2,
                                               const float* __restrict__ bg2)
{
    int b    = blockIdx.x * 4 + (threadIdx.x >> 5);
    int lane = threadIdx.x & 31;
    const float* grow = g_g + (long)b * GQ;

    float acc[8] = {0, 0, 0, 0, 0, 0, 0, 0};
    for (int k = lane; k < GQ; k += 32) {
        float gv = grow[k];
        const float* w = Wg2 + k * 8;
#pragma unroll
        for (int e = 0; e < 8; e++) acc[e] = fmaf(gv, w[e], acc[e]);
    }
#pragma unroll
    for (int e = 0; e < 8; e++) {
#pragma unroll
        for (int o = 16; o; o >>= 1) acc[e] += __shfl_xor_sync(0xffffffffu, acc[e], o);
    }
    if (lane == 0) {
        float l[8], m = -1e30f;
#pragma unroll
        for (int e = 0; e < 8; e++) { l[e] = acc[e] + bg2[e]; m = fmaxf(m, l[e]); }
        float s = 0.f;
#pragma unroll
        for (int e = 0; e < 8; e++) { l[e] = expf(l[e] - m); s += l[e]; }
        float inv = 1.f / s;
#pragma unroll
        for (int e = 0; e < 8; e++) { l[e] *= inv; g_gatew[b * 8 + e] = l[e]; }
        int i0 = 0;
#pragma unroll
        for (int e = 1; e < 8; e++) if (l[e] > l[i0]) i0 = e;
        int i1 = -1;
#pragma unroll
        for (int e = 0; e < 8; e++) {
            if (e == i0) continue;
            if (i1 < 0 || l[e] > l[i1]) i1 = e;
        }
        float w0 = l[i0], w1 = l[i1];
        float mm = fmaxf(w0, w1);
        float e0 = expf(w0 - mm), e1 = expf(w1 - mm);
        float si = 1.f / (e0 + e1);
        g_topidx[2 * b]     = i0;
        g_topidx[2 * b + 1] = i1;
        g_topw[2 * b]       = e0 * si;
        g_topw[2 * b + 1]   = e1 * si;
        atomicAdd(&g_cnt[i0], 1);
        atomicAdd(&g_cnt[i1], 1);
    }
}

__global__ void k_offsets()
{
    if (threadIdx.x == 0) {
        int s = 0, idx = 0;
        for (int e = 0; e < EQ; e++) {
            g_off[e] = s;
            int c = g_cnt[e];
            s += c;
            int nt = (c + TM - 1) / TM;
            for (int t = 0; t < nt; t++) g_tiles[idx++] = e | (t << 8);
        }
        g_off[EQ] = s;
        g_ntiles = idx;
    }
}

__global__ void k_scatter()
{
    int b = blockIdx.x * blockDim.x + threadIdx.x;
    if (b >= BQ) return;
#pragma unroll
    for (int s = 0; s < 2; s++) {
        int e = g_topidx[2 * b + s];
        int p = g_off[e] + atomicAdd(&g_cursor[e], 1);
        g_ptok[p]         = b;
        g_pidx[2 * b + s] = p;
    }
}

__global__ __launch_bounds__(256) void k_usage()
{
    int e = blockIdx.x, t = threadIdx.x;
    __shared__ float sh[256];
    float s = 0.f;
    for (int b = t; b < BQ; b += 256) s += g_gatew[b * 8 + e];
    sh[t] = s;
    __syncthreads();
    for (int o = 128; o; o >>= 1) {
        if (t < o) sh[t] += sh[t + o];
        __syncthreads();
    }
    if (t == 0) g_usage[e] = sh[0];
}

__global__ void k_loss(float* out, int out_size)
{
    if (threadIdx.x == 0 && out_size > BQ * DOUTQ) {
        float acc = 0.f;
        for (int e = 0; e < EQ; e++) {
            float d = g_usage[e] / (float)BQ - 1.0f / (float)EQ;
            acc += d * d;
        }
        out[BQ * DOUTQ] = acc / (float)EQ;
    }
}

__global__ __launch_bounds__(256) void k_combine(float* __restrict__ out)
{
    int b  = blockIdx.x;
    int p0 = g_pidx[2 * b], p1 = g_pidx[2 * b + 1];
    float w0 = g_topw[2 * b], w1 = g_topw[2 * b + 1];
    const float* y0 = g_y + (long)p0 * DOUTQ;
    const float* y1 = g_y + (long)p1 * DOUTQ;
    float* o = out + (long)b * DOUTQ;
    for (int d = threadIdx.x; d < DOUTQ; d += 256)
        o[d] = w0 * y0[d] + w1 * y1[d];
}

// ---------------- launch --------------------------------------------------
extern "C" void kernel_launch(void* const* d_in, const int* in_sizes, int n_in,
                              void* d_out, int out_size)
{
    const float* x   = (const float*)d_in[0];
    const float* W1  = (const float*)d_in[1];
    const float* b1  = (const float*)d_in[2];
    const float* W2  = (const float*)d_in[3];
    const float* b2  = (const float*)d_in[4];
    const float* W3  = (const float*)d_in[5];
    const float* b3  = (const float*)d_in[6];
    const float* Wg1 = (const float*)d_in[7];
    const float* bg1 = (const float*)d_in[8];
    const float* Wg2 = (const float*)d_in[9];
    const float* bg2 = (const float*)d_in[10];
    float* out = (float*)d_out;

    float *p_g, *p_y;
    int *p_goff, *p_gcnt, *p_ptok;
    __half *p_x, *p_w1h, *p_w2h, *p_w3h, *p_h1, *p_h2;
    cudaGetSymbolAddress((void**)&p_g,    g_g);
    cudaGetSymbolAddress((void**)&p_y,    g_y);
    cudaGetSymbolAddress((void**)&p_goff, g_gate_off);
    cudaGetSymbolAddress((void**)&p_gcnt, g_gate_cnt);
    cudaGetSymbolAddress((void**)&p_ptok, g_ptok);
    cudaGetSymbolAddress((void**)&p_x,    g_x);
    cudaGetSymbolAddress((void**)&p_w1h,  g_w1h);
    cudaGetSymbolAddress((void**)&p_w2h,  g_w2h);
    cudaGetSymbolAddress((void**)&p_w3h,  g_w3h);
    cudaGetSymbolAddress((void**)&p_h1,   g_h1);
    cudaGetSymbolAddress((void**)&p_h2,   g_h2);

    cudaFuncSetAttribute(moe_f16_gemm,
                         cudaFuncAttributeMaxDynamicSharedMemorySize, SMEM_SZ);

    k_zero<<<1, 32>>>();

    // pre-convert x and weights to fp16 (W transposed to [E][N][K])
    k_splitx<<<(BQ * DQ / 4 + 255) / 256, 256>>>(x);
    {
        dim3 g1(HQ / 32, DQ / 32, EQ);
        k_splitw<<<g1, 256>>>(W1, p_w1h, DQ, HQ);
        dim3 g2(H2Q / 32, HQ / 32, EQ);
        k_splitw<<<g2, 256>>>(W2, p_w2h, HQ, H2Q);
        dim3 g3(DOUTQ / 32, H2Q / 32, EQ);
        k_splitw<<<g3, 256>>>(W3, p_w3h, H2Q, DOUTQ);
    }

    // gate: g = relu(x @ Wg1 + bg1) then layer2 + softmax + top2 + routing
    {
        dim3 grid(GQ / 128, BQ / 128, 1);
        sgemm_seg<<<grid, 256>>>(x, Wg1, bg1, p_g, p_goff, p_gcnt, DQ, GQ, 1);
    }
    k_gate2<<<BQ / 4, 128>>>(Wg2, bg2);
    k_offsets<<<1, 32>>>();
    k_scatter<<<BQ / 256, 256>>>();
    k_usage<<<EQ, 256>>>();
    k_loss<<<1, 32>>>(out, out_size);

    // expert layer 1: h1 = relu(gather(x) @ W1h[e] + b1[e])  K=1024, N=4096
    {
        dim3 grid(HQ / TN, MAXTILES, 1);
        moe_f16_gemm<<<grid, 256, SMEM_SZ>>>(
            p_x, p_w1h, b1, p_h1, nullptr, p_ptok, DQ, HQ, 1);
    }
    // expert layer 2: h2 = relu(h1 @ W2h[e] + b2[e])  K=4096, N=2048
    {
        dim3 grid(H2Q / TN, MAXTILES, 1);
        moe_f16_gemm<<<grid, 256, SMEM_SZ>>>(
            p_h1, p_w2h, b2, p_h2, nullptr, nullptr, HQ, H2Q, 1);
    }
    // expert layer 3: y = h2 @ W3h[e] + b3[e]  K=2048, N=1024
    {
        dim3 grid(DOUTQ / TN, MAXTILES, 1);
        moe_f16_gemm<<<grid, 256, SMEM_SZ>>>(
            p_h2, p_w3h, b3, nullptr, p_y, nullptr, H2Q, DOUTQ, 0);
    }
    k_combine<<<BQ, 256>>>(out);
}

// round 13
// speedup vs baseline: 2.5223x; 1.0963x over previous
#include <cuda_runtime.h>
#include <cuda_fp16.h>
#include <math.h>
#include <stdint.h>

// Problem constants
#define BQ    8192
#define DQ    1024
#define HQ    4096
#define H2Q   2048
#define DOUTQ 1024
#define EQ    8
#define GQ    512
#define PAIRS (BQ * 2)
#define MAXTILES (PAIRS / 128 + EQ)   // 136

// ---------------- scratch (device globals) ---------------------------------
__device__ float g_g[BQ * GQ];
__device__ float g_y [PAIRS * DOUTQ];
__device__ float g_gatew[BQ * EQ];
__device__ int   g_topidx[BQ * 2];
__device__ float g_topw [BQ * 2];
__device__ int   g_cnt[EQ];
__device__ int   g_off[EQ + 1];
__device__ int   g_cursor[EQ];
__device__ int   g_ptok[PAIRS];
__device__ int   g_pidx[BQ * 2];
__device__ float g_usage[EQ];
__device__ int   g_tiles[MAXTILES];
__device__ int   g_ntiles;

// fp16 operands
__device__ __half g_x  [BQ * DQ];          // x hi
__device__ __half g_xl [BQ * DQ];          // x lo (gate only)
__device__ __half g_wg1h[GQ * DQ];         // Wg1^T hi
__device__ __half g_wg1l[GQ * DQ];         // Wg1^T lo
__device__ __half g_w1h[EQ * DQ * HQ];
__device__ __half g_w2h[EQ * HQ * H2Q];
__device__ __half g_w3h[EQ * H2Q * DOUTQ];
__device__ __half g_h1 [PAIRS * HQ];
__device__ __half g_h2 [PAIRS * H2Q];

// ---------------- helpers ---------------------------------------------------
__device__ __forceinline__ uint32_t smem_u32(const void* p) {
    uint32_t a;
    asm("{ .reg .u64 t; cvta.to.shared.u64 t, %1; cvt.u32.u64 %0, t; }"
        : "=r"(a) : "l"(p));
    return a;
}
__device__ __forceinline__ uint32_t sw64(uint32_t off) {
    return off ^ ((off >> 3) & 0x30);
}
__device__ __forceinline__ void ldsm_x4(uint32_t* r, uint32_t addr) {
    asm volatile("ldmatrix.sync.aligned.m8n8.x4.shared.b16 {%0,%1,%2,%3}, [%4];"
                 : "=r"(r[0]), "=r"(r[1]), "=r"(r[2]), "=r"(r[3]) : "r"(addr));
}
__device__ __forceinline__ void mma_f16(float* d, const uint32_t* a,
                                        uint32_t b0, uint32_t b1) {
    asm volatile(
        "mma.sync.aligned.m16n8k16.row.col.f32.f16.f16.f32 "
        "{%0,%1,%2,%3}, {%4,%5,%6,%7}, {%8,%9}, {%0,%1,%2,%3};"
        : "+f"(d[0]), "+f"(d[1]), "+f"(d[2]), "+f"(d[3])
        : "r"(a[0]), "r"(a[1]), "r"(a[2]), "r"(a[3]), "r"(b0), "r"(b1));
}
__device__ __forceinline__ void cpa16(uint32_t d, const void* s) {
    asm volatile("cp.async.cg.shared.global [%0], [%1], 16;" :: "r"(d), "l"(s));
}
#define CP_COMMIT() asm volatile("cp.async.commit_group;" ::: "memory")
#define CP_WAIT1()  asm volatile("cp.async.wait_group 1;" ::: "memory")
#define CP_WAIT0()  asm volatile("cp.async.wait_group 0;" ::: "memory")

#define TM 128
#define TN 128
#define TK 32

// ---------------- expert fp16 GEMM (single term) ----------------------------
#define O_A    0                 // 8192 bytes
#define O_BH   8192
#define STG_SZ 16384
#define SMEM_SZ (3 * STG_SZ)     // 49152

__global__ __launch_bounds__(256, 2) void moe_f16_gemm(
    const __half* __restrict__ Ax,
    const __half* __restrict__ Bh,
    const float* __restrict__ bias,
    __half* __restrict__ Chf,
    float* __restrict__ Cf,
    const int* __restrict__ rowmap,
    int K, int N, int relu)
{
    extern __shared__ char smem[];
    if ((int)blockIdx.y >= g_ntiles) return;
    const int d    = g_tiles[blockIdx.y];
    const int e    = d & 255;
    const int ts   = d >> 8;
    const int mseg = g_off[e];
    const int mend = mseg + g_cnt[e];
    const int m0   = mseg + ts * TM;
    const int n0   = blockIdx.x * TN;

    const __half* Bhe = Bh + (long)e * (long)N * (long)K;
    const float* bvec = bias + (long)e * N;

    const uint32_t sb = smem_u32(smem);
    const int tid  = threadIdx.x;
    const int wid  = tid >> 5;
    const int lane = tid & 31;
    const int wm   = wid & 3;
    const int wn   = wid >> 2;

    float acc[16][4];
#pragma unroll
    for (int i = 0; i < 16; i++)
#pragma unroll
        for (int j = 0; j < 4; j++) acc[i][j] = 0.f;

    const int lr = ((lane >> 3) & 1) * 8 + (lane & 7);
    const int lc = (lane >> 4) * 16;

    uint32_t offA[2][2], offB[2][4];
#pragma unroll
    for (int ks = 0; ks < 2; ks++) {
        const int kb = ks * 32 + lc;
#pragma unroll
        for (int mt = 0; mt < 2; mt++)
            offA[ks][mt] = sw64((uint32_t)((wm * 32 + mt * 16 + lr) * 64 + kb));
#pragma unroll
        for (int nt = 0; nt < 4; nt++)
            offB[ks][nt] = sw64((uint32_t)((wn * 64 + nt * 16 + lr) * 64 + kb));
    }

    const int nk = K / TK;

#define LOAD_CHUNK(kc_)                                                       \
    do {                                                                      \
        const uint32_t base_ = sb + ((kc_) % 3) * STG_SZ;                     \
        const int kbase_ = (kc_) * TK;                                        \
        _Pragma("unroll")                                                     \
        for (int i = 0; i < 2; i++) {                                         \
            int u = tid + i * 256;                                            \
            int r = u >> 2;                                                   \
            int c = u & 3;                                                    \
            int gm = m0 + r;                                                  \
            if (gm >= mend) gm = mend - 1;                                    \
            int src = rowmap ? rowmap[gm] : gm;                               \
            const __half* g = Ax + (long)src * K + kbase_ + c * 8;            \
            uint32_t dd = base_ + O_A + sw64((uint32_t)(r * 64 + c * 16));    \
            cpa16(dd, g);                                                     \
        }                                                                     \
        _Pragma("unroll")                                                     \
        for (int i = 0; i < 2; i++) {                                         \
            int u = tid + i * 256;                                            \
            int r = u >> 2;                                                   \
            int c = u & 3;                                                    \
            const __half* g = Bhe + (long)(n0 + r) * K + kbase_ + c * 8;      \
            uint32_t dd = base_ + O_BH + sw64((uint32_t)(r * 64 + c * 16));   \
            cpa16(dd, g);                                                     \
        }                                                                     \
        CP_COMMIT();                                                          \
    } while (0)

    LOAD_CHUNK(0);
    if (nk > 1) LOAD_CHUNK(1);

    for (int kc = 0; kc < nk; kc++) {
        if (kc == nk - 1) { CP_WAIT0(); } else { CP_WAIT1(); }
        __syncthreads();
        if (kc + 2 < nk) LOAD_CHUNK(kc + 2);

        const uint32_t base = sb + (kc % 3) * STG_SZ;
#pragma unroll
        for (int ks = 0; ks < 2; ks++) {
            uint32_t af[2][4], bfrag[4][4];
#pragma unroll
            for (int mt = 0; mt < 2; mt++)
                ldsm_x4(af[mt], base + O_A + offA[ks][mt]);
#pragma unroll
            for (int nt = 0; nt < 4; nt++)
                ldsm_x4(bfrag[nt], base + O_BH + offB[ks][nt]);
#pragma unroll
            for (int mt = 0; mt < 2; mt++)
#pragma unroll
                for (int nt = 0; nt < 4; nt++) {
                    mma_f16(acc[mt * 8 + nt * 2 + 0], af[mt], bfrag[nt][0], bfrag[nt][2]);
                    mma_f16(acc[mt * 8 + nt * 2 + 1], af[mt], bfrag[nt][1], bfrag[nt][3]);
                }
        }
    }
#undef LOAD_CHUNK

#pragma unroll
    for (int mt = 0; mt < 2; mt++) {
#pragma unroll
        for (int nt = 0; nt < 8; nt++) {
            const float* a4 = acc[mt * 8 + nt];
            int col  = n0 + wn * 64 + nt * 8 + ((lane & 3) << 1);
            float bb0 = bvec[col], bb1 = bvec[col + 1];
            int row0 = m0 + wm * 32 + mt * 16 + (lane >> 2);
            int row1 = row0 + 8;
            float v0 = a4[0] + bb0, v1 = a4[1] + bb1;
            float v2 = a4[2] + bb0, v3 = a4[3] + bb1;
            if (relu) {
                v0 = fmaxf(v0, 0.f); v1 = fmaxf(v1, 0.f);
                v2 = fmaxf(v2, 0.f); v3 = fmaxf(v3, 0.f);
            }
            if (Cf) {
                if (row0 < mend)
                    *reinterpret_cast<float2*>(Cf + (long)row0 * N + col) = make_float2(v0, v1);
                if (row1 < mend)
                    *reinterpret_cast<float2*>(Cf + (long)row1 * N + col) = make_float2(v2, v3);
            } else {
                if (row0 < mend) {
                    __half2 h;
                    h.x = __float2half_rn(v0); h.y = __float2half_rn(v1);
                    *reinterpret_cast<uint32_t*>(Chf + (long)row0 * N + col) =
                        *reinterpret_cast<uint32_t*>(&h);
                }
                if (row1 < mend) {
                    __half2 h;
                    h.x = __float2half_rn(v2); h.y = __float2half_rn(v3);
                    *reinterpret_cast<uint32_t*>(Chf + (long)row1 * N + col) =
                        *reinterpret_cast<uint32_t*>(&h);
                }
            }
        }
    }
}

// ---------------- gate layer-1 GEMM (3-term fp16, ~fp32 precision) ----------
// g = relu(x @ Wg1 + bg1): ah*bh + al*bh + ah*bl, error ~2^-22 (routing-safe)
#define GO_AH  0
#define GO_AL  8192
#define GO_BH  16384
#define GO_BL  24576
#define GSTG   32768
#define GSMEM  (3 * GSTG)        // 98304

__global__ __launch_bounds__(256, 2) void gate_f16_gemm(
    const float* __restrict__ bias)
{
    extern __shared__ char smem[];
    const int m0 = blockIdx.y * TM;
    const int n0 = blockIdx.x * TN;
    const int K  = DQ, N = GQ;

    const uint32_t sb = smem_u32(smem);
    const int tid  = threadIdx.x;
    const int wid  = tid >> 5;
    const int lane = tid & 31;
    const int wm   = wid & 3;
    const int wn   = wid >> 2;

    float acc[16][4];
#pragma unroll
    for (int i = 0; i < 16; i++)
#pragma unroll
        for (int j = 0; j < 4; j++) acc[i][j] = 0.f;

    const int lr = ((lane >> 3) & 1) * 8 + (lane & 7);
    const int lc = (lane >> 4) * 16;

    uint32_t offA[2][2], offB[2][4];
#pragma unroll
    for (int ks = 0; ks < 2; ks++) {
        const int kb = ks * 32 + lc;
#pragma unroll
        for (int mt = 0; mt < 2; mt++)
            offA[ks][mt] = sw64((uint32_t)((wm * 32 + mt * 16 + lr) * 64 + kb));
#pragma unroll
        for (int nt = 0; nt < 4; nt++)
            offB[ks][nt] = sw64((uint32_t)((wn * 64 + nt * 16 + lr) * 64 + kb));
    }

    const int nk = K / TK;   // 32

#define GLOAD(kc_)                                                            \
    do {                                                                      \
        const uint32_t base_ = sb + ((kc_) % 3) * GSTG;                       \
        const int kbase_ = (kc_) * TK;                                        \
        _Pragma("unroll")                                                     \
        for (int i = 0; i < 4; i++) {     /* A hi+lo */                       \
            int u     = tid + i * 256;                                        \
            int half_ = u >> 9;                                               \
            int v     = u & 511;                                              \
            int r     = v >> 2;                                               \
            int c     = v & 3;                                                \
            const __half* g = (half_ ? g_xl : g_x) + (long)(m0 + r) * K + kbase_ + c * 8; \
            uint32_t dd = base_ + (half_ ? GO_AL : GO_AH) + sw64((uint32_t)(r * 64 + c * 16)); \
            cpa16(dd, g);                                                     \
        }                                                                     \
        _Pragma("unroll")                                                     \
        for (int i = 0; i < 4; i++) {     /* B hi+lo */                       \
            int u     = tid + i * 256;                                        \
            int half_ = u >> 9;                                               \
            int v     = u & 511;                                              \
            int r     = v >> 2;                                               \
            int c     = v & 3;                                                \
            const __half* g = (half_ ? g_wg1l : g_wg1h) + (long)(n0 + r) * K + kbase_ + c * 8; \
            uint32_t dd = base_ + (half_ ? GO_BL : GO_BH) + sw64((uint32_t)(r * 64 + c * 16)); \
            cpa16(dd, g);                                                     \
        }                                                                     \
        CP_COMMIT();                                                          \
    } while (0)

    GLOAD(0);
    GLOAD(1);

    for (int kc = 0; kc < nk; kc++) {
        if (kc == nk - 1) { CP_WAIT0(); } else { CP_WAIT1(); }
        __syncthreads();
        if (kc + 2 < nk) GLOAD(kc + 2);

        const uint32_t base = sb + (kc % 3) * GSTG;
#pragma unroll
        for (int ks = 0; ks < 2; ks++) {
            uint32_t ah[2][4], al[2][4], bfrag[4][4];
#pragma unroll
            for (int mt = 0; mt < 2; mt++) {
                ldsm_x4(ah[mt], base + GO_AH + offA[ks][mt]);
                ldsm_x4(al[mt], base + GO_AL + offA[ks][mt]);
            }
#pragma unroll
            for (int nt = 0; nt < 4; nt++)
                ldsm_x4(bfrag[nt], base + GO_BH + offB[ks][nt]);
            // pass 1: ah*bh
#pragma unroll
            for (int mt = 0; mt < 2; mt++)
#pragma unroll
                for (int nt = 0; nt < 4; nt++) {
                    mma_f16(acc[mt * 8 + nt * 2 + 0], ah[mt], bfrag[nt][0], bfrag[nt][2]);
                    mma_f16(acc[mt * 8 + nt * 2 + 1], ah[mt], bfrag[nt][1], bfrag[nt][3]);
                }
            // pass 2: al*bh
#pragma unroll
            for (int mt = 0; mt < 2; mt++)
#pragma unroll
                for (int nt = 0; nt < 4; nt++) {
                    mma_f16(acc[mt * 8 + nt * 2 + 0], al[mt], bfrag[nt][0], bfrag[nt][2]);
                    mma_f16(acc[mt * 8 + nt * 2 + 1], al[mt], bfrag[nt][1], bfrag[nt][3]);
                }
            // pass 3: ah*bl
#pragma unroll
            for (int nt = 0; nt < 4; nt++)
                ldsm_x4(bfrag[nt], base + GO_BL + offB[ks][nt]);
#pragma unroll
            for (int mt = 0; mt < 2; mt++)
#pragma unroll
                for (int nt = 0; nt < 4; nt++) {
                    mma_f16(acc[mt * 8 + nt * 2 + 0], ah[mt], bfrag[nt][0], bfrag[nt][2]);
                    mma_f16(acc[mt * 8 + nt * 2 + 1], ah[mt], bfrag[nt][1], bfrag[nt][3]);
                }
        }
    }
#undef GLOAD

    // epilogue: bias + relu -> fp32 g_g
#pragma unroll
    for (int mt = 0; mt < 2; mt++) {
#pragma unroll
        for (int nt = 0; nt < 8; nt++) {
            const float* a4 = acc[mt * 8 + nt];
            int col  = n0 + wn * 64 + nt * 8 + ((lane & 3) << 1);
            float bb0 = bias[col], bb1 = bias[col + 1];
            int row0 = m0 + wm * 32 + mt * 16 + (lane >> 2);
            int row1 = row0 + 8;
            float v0 = fmaxf(a4[0] + bb0, 0.f), v1 = fmaxf(a4[1] + bb1, 0.f);
            float v2 = fmaxf(a4[2] + bb0, 0.f), v3 = fmaxf(a4[3] + bb1, 0.f);
            *reinterpret_cast<float2*>(g_g + (long)row0 * N + col) = make_float2(v0, v1);
            *reinterpret_cast<float2*>(g_g + (long)row1 * N + col) = make_float2(v2, v3);
        }
    }
}

// ---------------- pre-passes ------------------------------------------------
// x -> fp16 hi + lo
__global__ __launch_bounds__(256) void k_splitx(const float* __restrict__ x)
{
    long i = (long)(blockIdx.x * 256 + threadIdx.x) * 4;
    if (i >= (long)BQ * DQ) return;
    float4 v = *reinterpret_cast<const float4*>(x + i);
    __half2 h0, h1, l0, l1;
    h0.x = __float2half_rn(v.x); h0.y = __float2half_rn(v.y);
    h1.x = __float2half_rn(v.z); h1.y = __float2half_rn(v.w);
    l0.x = __float2half_rn(v.x - __half2float(h0.x));
    l0.y = __float2half_rn(v.y - __half2float(h0.y));
    l1.x = __float2half_rn(v.z - __half2float(h1.x));
    l1.y = __float2half_rn(v.w - __half2float(h1.y));
    *reinterpret_cast<uint2*>(g_x + i) = make_uint2(
        *reinterpret_cast<uint32_t*>(&h0), *reinterpret_cast<uint32_t*>(&h1));
    *reinterpret_cast<uint2*>(g_xl + i) = make_uint2(
        *reinterpret_cast<uint32_t*>(&l0), *reinterpret_cast<uint32_t*>(&l1));
}

// W [E][K][N] f32 -> Wh [E][N][K] fp16; 64k x 32n tile, 16B stores
__global__ __launch_bounds__(256) void k_splitw(
    const float* __restrict__ src, __half* __restrict__ dh, int K, int N)
{
    __shared__ float t[64][33];
    const int e  = blockIdx.z;
    const int n0 = blockIdx.x * 32;
    const int k0 = blockIdx.y * 64;
    const int tid = threadIdx.x;
    const float* S = src + (long)e * K * N;
#pragma unroll
    for (int i = 0; i < 2; i++) {
        int kr = (tid >> 3) + i * 32;
        int n4 = tid & 7;
        float4 v = *reinterpret_cast<const float4*>(S + (long)(k0 + kr) * N + n0 + n4 * 4);
        t[kr][n4 * 4 + 0] = v.x;
        t[kr][n4 * 4 + 1] = v.y;
        t[kr][n4 * 4 + 2] = v.z;
        t[kr][n4 * 4 + 3] = v.w;
    }
    __syncthreads();
    {
        int n = tid >> 3, kq = tid & 7;
        uint4 u;
        uint32_t* up = reinterpret_cast<uint32_t*>(&u);
#pragma unroll
        for (int j = 0; j < 4; j++) {
            __half2 h;
            h.x = __float2half_rn(t[kq * 8 + j * 2 + 0][n]);
            h.y = __float2half_rn(t[kq * 8 + j * 2 + 1][n]);
            up[j] = *reinterpret_cast<uint32_t*>(&h);
        }
        long o = (long)e * N * K + (long)(n0 + n) * K + k0 + kq * 8;
        *reinterpret_cast<uint4*>(dh + o) = u;
    }
}

// Wg1 [K=1024][N=512] f32 -> [N][K] fp16 hi + lo (32x32 transpose)
__global__ __launch_bounds__(256) void k_splitwg(const float* __restrict__ src)
{
    __shared__ float t[32][33];
    const int n0 = blockIdx.x * 32;
    const int k0 = blockIdx.y * 32;
    const int tid = threadIdx.x;
    {
        int kr = tid >> 3, n4 = tid & 7;
        float4 v = *reinterpret_cast<const float4*>(src + (long)(k0 + kr) * GQ + n0 + n4 * 4);
        t[kr][n4 * 4 + 0] = v.x;
        t[kr][n4 * 4 + 1] = v.y;
        t[kr][n4 * 4 + 2] = v.z;
        t[kr][n4 * 4 + 3] = v.w;
    }
    __syncthreads();
    {
        int n = tid >> 3, kq = tid & 7;
        float v0 = t[kq * 4 + 0][n], v1 = t[kq * 4 + 1][n];
        float v2 = t[kq * 4 + 2][n], v3 = t[kq * 4 + 3][n];
        __half2 h0, h1, l0, l1;
        h0.x = __float2half_rn(v0); h0.y = __float2half_rn(v1);
        h1.x = __float2half_rn(v2); h1.y = __float2half_rn(v3);
        l0.x = __float2half_rn(v0 - __half2float(h0.x));
        l0.y = __float2half_rn(v1 - __half2float(h0.y));
        l1.x = __float2half_rn(v2 - __half2float(h1.x));
        l1.y = __float2half_rn(v3 - __half2float(h1.y));
        long o = (long)(n0 + n) * DQ + k0 + kq * 4;
        *reinterpret_cast<uint2*>(g_wg1h + o) = make_uint2(
            *reinterpret_cast<uint32_t*>(&h0), *reinterpret_cast<uint32_t*>(&h1));
        *reinterpret_cast<uint2*>(g_wg1l + o) = make_uint2(
            *reinterpret_cast<uint32_t*>(&l0), *reinterpret_cast<uint32_t*>(&l1));
    }
}

// ---------------- small kernels ------------------------------------------
__global__ void k_zero()
{
    int t = threadIdx.x;
    if (t < EQ) { g_cnt[t] = 0; g_cursor[t] = 0; }
}

__global__ __launch_bounds__(128) void k_gate2(const float* __restrict__ Wg2,
                                               const float* __restrict__ bg2)
{
    int b    = blockIdx.x * 4 + (threadIdx.x >> 5);
    int lane = threadIdx.x & 31;
    const float* grow = g_g + (long)b * GQ;

    float acc[8] = {0, 0, 0, 0, 0, 0, 0, 0};
    for (int k = lane; k < GQ; k += 32) {
        float gv = grow[k];
        const float* w = Wg2 + k * 8;
#pragma unroll
        for (int e = 0; e < 8; e++) acc[e] = fmaf(gv, w[e], acc[e]);
    }
#pragma unroll
    for (int e = 0; e < 8; e++) {
#pragma unroll
        for (int o = 16; o; o >>= 1) acc[e] += __shfl_xor_sync(0xffffffffu, acc[e], o);
    }
    if (lane == 0) {
        float l[8], m = -1e30f;
#pragma unroll
        for (int e = 0; e < 8; e++) { l[e] = acc[e] + bg2[e]; m = fmaxf(m, l[e]); }
        float s = 0.f;
#pragma unroll
        for (int e = 0; e < 8; e++) { l[e] = expf(l[e] - m); s += l[e]; }
        float inv = 1.f / s;
#pragma unroll
        for (int e = 0; e < 8; e++) { l[e] *= inv; g_gatew[b * 8 + e] = l[e]; }
        int i0 = 0;
#pragma unroll
        for (int e = 1; e < 8; e++) if (l[e] > l[i0]) i0 = e;
        int i1 = -1;
#pragma unroll
        for (int e = 0; e < 8; e++) {
            if (e == i0) continue;
            if (i1 < 0 || l[e] > l[i1]) i1 = e;
        }
        float w0 = l[i0], w1 = l[i1];
        float mm = fmaxf(w0, w1);
        float e0 = expf(w0 - mm), e1 = expf(w1 - mm);
        float si = 1.f / (e0 + e1);
        g_topidx[2 * b]     = i0;
        g_topidx[2 * b + 1] = i1;
        g_topw[2 * b]       = e0 * si;
        g_topw[2 * b + 1]   = e1 * si;
        atomicAdd(&g_cnt[i0], 1);
        atomicAdd(&g_cnt[i1], 1);
    }
}

__global__ void k_offsets()
{
    if (threadIdx.x == 0) {
        int s = 0, idx = 0;
        for (int e = 0; e < EQ; e++) {
            g_off[e] = s;
            int c = g_cnt[e];
            s += c;
            int nt = (c + TM - 1) / TM;
            for (int t = 0; t < nt; t++) g_tiles[idx++] = e | (t << 8);
        }
        g_off[EQ] = s;
        g_ntiles = idx;
    }
}

__global__ void k_scatter()
{
    int b = blockIdx.x * blockDim.x + threadIdx.x;
    if (b >= BQ) return;
#pragma unroll
    for (int s = 0; s < 2; s++) {
        int e = g_topidx[2 * b + s];
        int p = g_off[e] + atomicAdd(&g_cursor[e], 1);
        g_ptok[p]         = b;
        g_pidx[2 * b + s] = p;
    }
}

__global__ __launch_bounds__(256) void k_usage()
{
    int e = blockIdx.x, t = threadIdx.x;
    __shared__ float sh[256];
    float s = 0.f;
    for (int b = t; b < BQ; b += 256) s += g_gatew[b * 8 + e];
    sh[t] = s;
    __syncthreads();
    for (int o = 128; o; o >>= 1) {
        if (t < o) sh[t] += sh[t + o];
        __syncthreads();
    }
    if (t == 0) g_usage[e] = sh[0];
}

__global__ void k_loss(float* out, int out_size)
{
    if (threadIdx.x == 0 && out_size > BQ * DOUTQ) {
        float acc = 0.f;
        for (int e = 0; e < EQ; e++) {
            float d = g_usage[e] / (float)BQ - 1.0f / (float)EQ;
            acc += d * d;
        }
        out[BQ * DOUTQ] = acc / (float)EQ;
    }
}

__global__ __launch_bounds__(256) void k_combine(float* __restrict__ out)
{
    int b  = blockIdx.x;
    int p0 = g_pidx[2 * b], p1 = g_pidx[2 * b + 1];
    float w0 = g_topw[2 * b], w1 = g_topw[2 * b + 1];
    const float* y0 = g_y + (long)p0 * DOUTQ;
    const float* y1 = g_y + (long)p1 * DOUTQ;
    float* o = out + (long)b * DOUTQ;
    for (int d = threadIdx.x; d < DOUTQ; d += 256)
        o[d] = w0 * y0[d] + w1 * y1[d];
}

// ---------------- launch --------------------------------------------------
extern "C" void kernel_launch(void* const* d_in, const int* in_sizes, int n_in,
                              void* d_out, int out_size)
{
    const float* x   = (const float*)d_in[0];
    const float* W1  = (const float*)d_in[1];
    const float* b1  = (const float*)d_in[2];
    const float* W2  = (const float*)d_in[3];
    const float* b2  = (const float*)d_in[4];
    const float* W3  = (const float*)d_in[5];
    const float* b3  = (const float*)d_in[6];
    const float* Wg1 = (const float*)d_in[7];
    const float* bg1 = (const float*)d_in[8];
    const float* Wg2 = (const float*)d_in[9];
    const float* bg2 = (const float*)d_in[10];
    float* out = (float*)d_out;

    float* p_y;
    int* p_ptok;
    __half *p_x, *p_w1h, *p_w2h, *p_w3h, *p_h1, *p_h2;
    cudaGetSymbolAddress((void**)&p_y,    g_y);
    cudaGetSymbolAddress((void**)&p_ptok, g_ptok);
    cudaGetSymbolAddress((void**)&p_x,    g_x);
    cudaGetSymbolAddress((void**)&p_w1h,  g_w1h);
    cudaGetSymbolAddress((void**)&p_w2h,  g_w2h);
    cudaGetSymbolAddress((void**)&p_w3h,  g_w3h);
    cudaGetSymbolAddress((void**)&p_h1,   g_h1);
    cudaGetSymbolAddress((void**)&p_h2,   g_h2);

    cudaFuncSetAttribute(moe_f16_gemm,
                         cudaFuncAttributeMaxDynamicSharedMemorySize, SMEM_SZ);
    cudaFuncSetAttribute(gate_f16_gemm,
                         cudaFuncAttributeMaxDynamicSharedMemorySize, GSMEM);

    k_zero<<<1, 32>>>();

    // pre-convert inputs
    k_splitx<<<(BQ * DQ / 4 + 255) / 256, 256>>>(x);
    k_splitwg<<<dim3(GQ / 32, DQ / 32, 1), 256>>>(Wg1);
    k_splitw<<<dim3(HQ / 32, DQ / 64, EQ), 256>>>(W1, p_w1h, DQ, HQ);
    k_splitw<<<dim3(H2Q / 32, HQ / 64, EQ), 256>>>(W2, p_w2h, HQ, H2Q);
    k_splitw<<<dim3(DOUTQ / 32, H2Q / 64, EQ), 256>>>(W3, p_w3h, H2Q, DOUTQ);

    // gate: 3-term fp16 HMMA (fp32-accurate) -> softmax/top2/routing
    gate_f16_gemm<<<dim3(GQ / TN, BQ / TM, 1), 256, GSMEM>>>(bg1);
    k_gate2<<<BQ / 4, 128>>>(Wg2, bg2);
    k_offsets<<<1, 32>>>();
    k_scatter<<<BQ / 256, 256>>>();
    k_usage<<<EQ, 256>>>();
    k_loss<<<1, 32>>>(out, out_size);

    // expert layers
    {
        dim3 grid(HQ / TN, MAXTILES, 1);
        moe_f16_gemm<<<grid, 256, SMEM_SZ>>>(
            p_x, p_w1h, b1, p_h1, nullptr, p_ptok, DQ, HQ, 1);
    }
    {
        dim3 grid(H2Q / TN, MAXTILES, 1);
        moe_f16_gemm<<<grid, 256, SMEM_SZ>>>(
            p_h1, p_w2h, b2, p_h2, nullptr, nullptr, HQ, H2Q, 1);
    }
    {
        dim3 grid(DOUTQ / TN, MAXTILES, 1);
        moe_f16_gemm<<<grid, 256, SMEM_SZ>>>(
            p_h2, p_w3h, b3, nullptr, p_y, nullptr, H2Q, DOUTQ, 0);
    }
    k_combine<<<BQ, 256>>>(out);
}

// round 14
// speedup vs baseline: 2.7172x; 1.0773x over previous
#include <cuda_runtime.h>
#include <cuda_fp16.h>
#include <math.h>
#include <stdint.h>

// Problem constants
#define BQ    8192
#define DQ    1024
#define HQ    4096
#define H2Q   2048
#define DOUTQ 1024
#define EQ    8
#define GQ    512
#define PAIRS (BQ * 2)
#define MAXTILES (PAIRS / 128 + EQ)   // 136

// ---------------- scratch (device globals) ---------------------------------
__device__ float g_g[BQ * GQ];
__device__ float g_y [PAIRS * DOUTQ];
__device__ float g_gatew[BQ * EQ];
__device__ int   g_topidx[BQ * 2];
__device__ float g_topw [BQ * 2];
__device__ int   g_cnt[EQ];
__device__ int   g_off[EQ + 1];
__device__ int   g_cursor[EQ];
__device__ int   g_ptok[PAIRS];
__device__ int   g_pidx[BQ * 2];
__device__ float g_usage[EQ];
__device__ int   g_tiles[MAXTILES];
__device__ int   g_ntiles;

// fp16 operands
__device__ __half g_x  [BQ * DQ];          // x hi
__device__ __half g_xl [BQ * DQ];          // x lo (gate only)
__device__ __half g_wg1h[GQ * DQ];         // Wg1^T hi
__device__ __half g_wg1l[GQ * DQ];         // Wg1^T lo
__device__ __half g_w1h[EQ * DQ * HQ];
__device__ __half g_w2h[EQ * HQ * H2Q];
__device__ __half g_w3h[EQ * H2Q * DOUTQ];
__device__ __half g_h1 [PAIRS * HQ];
__device__ __half g_h2 [PAIRS * H2Q];

// ---------------- helpers ---------------------------------------------------
__device__ __forceinline__ uint32_t smem_u32(const void* p) {
    uint32_t a;
    asm("{ .reg .u64 t; cvta.to.shared.u64 t, %1; cvt.u32.u64 %0, t; }"
        : "=r"(a) : "l"(p));
    return a;
}
__device__ __forceinline__ uint32_t sw64(uint32_t off) {
    return off ^ ((off >> 3) & 0x30);
}
__device__ __forceinline__ uint32_t sw128(uint32_t off) {
    return off ^ ((off >> 3) & 0x70);
}
__device__ __forceinline__ void ldsm_x4(uint32_t* r, uint32_t addr) {
    asm volatile("ldmatrix.sync.aligned.m8n8.x4.shared.b16 {%0,%1,%2,%3}, [%4];"
                 : "=r"(r[0]), "=r"(r[1]), "=r"(r[2]), "=r"(r[3]) : "r"(addr));
}
__device__ __forceinline__ void mma_f16(float* d, const uint32_t* a,
                                        uint32_t b0, uint32_t b1) {
    asm volatile(
        "mma.sync.aligned.m16n8k16.row.col.f32.f16.f16.f32 "
        "{%0,%1,%2,%3}, {%4,%5,%6,%7}, {%8,%9}, {%0,%1,%2,%3};"
        : "+f"(d[0]), "+f"(d[1]), "+f"(d[2]), "+f"(d[3])
        : "r"(a[0]), "r"(a[1]), "r"(a[2]), "r"(a[3]), "r"(b0), "r"(b1));
}
__device__ __forceinline__ void cpa16(uint32_t d, const void* s) {
    asm volatile("cp.async.cg.shared.global [%0], [%1], 16;" :: "r"(d), "l"(s));
}
#define CP_COMMIT() asm volatile("cp.async.commit_group;" ::: "memory")
#define CP_WAIT1()  asm volatile("cp.async.wait_group 1;" ::: "memory")
#define CP_WAIT0()  asm volatile("cp.async.wait_group 0;" ::: "memory")

#define TM 128
#define TN 128

// ---------------- expert fp16 GEMM (single term, TK=64) ---------------------
#define TKE    64
#define O_A    0                 // 128 rows x 128B = 16384
#define O_B    16384
#define STG_SZ 32768
#define SMEM_SZ (3 * STG_SZ)     // 98304

__global__ __launch_bounds__(256, 2) void moe_f16_gemm(
    const __half* __restrict__ Ax,
    const __half* __restrict__ Bh,
    const float* __restrict__ bias,
    __half* __restrict__ Chf,
    float* __restrict__ Cf,
    const int* __restrict__ rowmap,
    int K, int N, int relu)
{
    extern __shared__ char smem[];
    if ((int)blockIdx.y >= g_ntiles) return;
    const int d    = g_tiles[blockIdx.y];
    const int e    = d & 255;
    const int ts   = d >> 8;
    const int mseg = g_off[e];
    const int mend = mseg + g_cnt[e];
    const int m0   = mseg + ts * TM;
    const int n0   = blockIdx.x * TN;

    const __half* Bhe = Bh + (long)e * (long)N * (long)K;
    const float* bvec = bias + (long)e * N;

    const uint32_t sb = smem_u32(smem);
    const int tid  = threadIdx.x;
    const int wid  = tid >> 5;
    const int lane = tid & 31;
    const int wm   = wid & 3;
    const int wn   = wid >> 2;

    float acc[16][4];
#pragma unroll
    for (int i = 0; i < 16; i++)
#pragma unroll
        for (int j = 0; j < 4; j++) acc[i][j] = 0.f;

    const int lr = ((lane >> 3) & 1) * 8 + (lane & 7);
    const int lc = (lane >> 4) * 16;

    // base swizzled offsets (ks-step applied via XOR of ks*32)
    uint32_t offA[2], offB[4];
#pragma unroll
    for (int mt = 0; mt < 2; mt++)
        offA[mt] = sw128((uint32_t)((wm * 32 + mt * 16 + lr) * 128 + lc));
#pragma unroll
    for (int nt = 0; nt < 4; nt++)
        offB[nt] = sw128((uint32_t)((wn * 64 + nt * 16 + lr) * 128 + lc));

    const int nk = K / TKE;

#define LOAD_CHUNK(kc_)                                                       \
    do {                                                                      \
        const uint32_t base_ = sb + ((kc_) % 3) * STG_SZ;                     \
        const int kbase_ = (kc_) * TKE;                                       \
        _Pragma("unroll")                                                     \
        for (int i = 0; i < 4; i++) {        /* A: 1024 16B chunks */         \
            int u = tid + i * 256;                                            \
            int r = u >> 3;                                                   \
            int c = u & 7;                                                    \
            int gm = m0 + r;                                                  \
            if (gm >= mend) gm = mend - 1;                                    \
            int src = rowmap ? rowmap[gm] : gm;                               \
            const __half* g = Ax + (long)src * K + kbase_ + c * 8;            \
            uint32_t dd = base_ + O_A + sw128((uint32_t)(r * 128 + c * 16));  \
            cpa16(dd, g);                                                     \
        }                                                                     \
        _Pragma("unroll")                                                     \
        for (int i = 0; i < 4; i++) {        /* B: 1024 16B chunks */         \
            int u = tid + i * 256;                                            \
            int r = u >> 3;                                                   \
            int c = u & 7;                                                    \
            const __half* g = Bhe + (long)(n0 + r) * K + kbase_ + c * 8;      \
            uint32_t dd = base_ + O_B + sw128((uint32_t)(r * 128 + c * 16));  \
            cpa16(dd, g);                                                     \
        }                                                                     \
        CP_COMMIT();                                                          \
    } while (0)

    LOAD_CHUNK(0);
    if (nk > 1) LOAD_CHUNK(1);

    for (int kc = 0; kc < nk; kc++) {
        if (kc == nk - 1) { CP_WAIT0(); } else { CP_WAIT1(); }
        __syncthreads();
        if (kc + 2 < nk) LOAD_CHUNK(kc + 2);

        const uint32_t base = sb + (kc % 3) * STG_SZ;
#pragma unroll
        for (int ks = 0; ks < 4; ks++) {
            const uint32_t kx = (uint32_t)(ks << 5);
            uint32_t af[2][4], bfrag[4][4];
#pragma unroll
            for (int mt = 0; mt < 2; mt++)
                ldsm_x4(af[mt], base + O_A + (offA[mt] ^ kx));
#pragma unroll
            for (int nt = 0; nt < 4; nt++)
                ldsm_x4(bfrag[nt], base + O_B + (offB[nt] ^ kx));
#pragma unroll
            for (int mt = 0; mt < 2; mt++)
#pragma unroll
                for (int nt = 0; nt < 4; nt++) {
                    mma_f16(acc[mt * 8 + nt * 2 + 0], af[mt], bfrag[nt][0], bfrag[nt][2]);
                    mma_f16(acc[mt * 8 + nt * 2 + 1], af[mt], bfrag[nt][1], bfrag[nt][3]);
                }
        }
    }
#undef LOAD_CHUNK

#pragma unroll
    for (int mt = 0; mt < 2; mt++) {
#pragma unroll
        for (int nt = 0; nt < 8; nt++) {
            const float* a4 = acc[mt * 8 + nt];
            int col  = n0 + wn * 64 + nt * 8 + ((lane & 3) << 1);
            float bb0 = bvec[col], bb1 = bvec[col + 1];
            int row0 = m0 + wm * 32 + mt * 16 + (lane >> 2);
            int row1 = row0 + 8;
            float v0 = a4[0] + bb0, v1 = a4[1] + bb1;
            float v2 = a4[2] + bb0, v3 = a4[3] + bb1;
            if (relu) {
                v0 = fmaxf(v0, 0.f); v1 = fmaxf(v1, 0.f);
                v2 = fmaxf(v2, 0.f); v3 = fmaxf(v3, 0.f);
            }
            if (Cf) {
                if (row0 < mend)
                    *reinterpret_cast<float2*>(Cf + (long)row0 * N + col) = make_float2(v0, v1);
                if (row1 < mend)
                    *reinterpret_cast<float2*>(Cf + (long)row1 * N + col) = make_float2(v2, v3);
            } else {
                if (row0 < mend) {
                    __half2 h;
                    h.x = __float2half_rn(v0); h.y = __float2half_rn(v1);
                    *reinterpret_cast<uint32_t*>(Chf + (long)row0 * N + col) =
                        *reinterpret_cast<uint32_t*>(&h);
                }
                if (row1 < mend) {
                    __half2 h;
                    h.x = __float2half_rn(v2); h.y = __float2half_rn(v3);
                    *reinterpret_cast<uint32_t*>(Chf + (long)row1 * N + col) =
                        *reinterpret_cast<uint32_t*>(&h);
                }
            }
        }
    }
}

// ---------------- gate layer-1 GEMM (3-term fp16, ~fp32 precision) ----------
#define GO_AH  0
#define GO_AL  8192
#define GO_BH  16384
#define GO_BL  24576
#define GSTG   32768
#define GSMEM  (3 * GSTG)        // 98304
#define GTK    32

__global__ __launch_bounds__(256, 2) void gate_f16_gemm(
    const float* __restrict__ bias)
{
    extern __shared__ char smem[];
    const int m0 = blockIdx.y * TM;
    const int n0 = blockIdx.x * TN;
    const int K  = DQ, N = GQ;

    const uint32_t sb = smem_u32(smem);
    const int tid  = threadIdx.x;
    const int wid  = tid >> 5;
    const int lane = tid & 31;
    const int wm   = wid & 3;
    const int wn   = wid >> 2;

    float acc[16][4];
#pragma unroll
    for (int i = 0; i < 16; i++)
#pragma unroll
        for (int j = 0; j < 4; j++) acc[i][j] = 0.f;

    const int lr = ((lane >> 3) & 1) * 8 + (lane & 7);
    const int lc = (lane >> 4) * 16;

    uint32_t offA[2][2], offB[2][4];
#pragma unroll
    for (int ks = 0; ks < 2; ks++) {
        const int kb = ks * 32 + lc;
#pragma unroll
        for (int mt = 0; mt < 2; mt++)
            offA[ks][mt] = sw64((uint32_t)((wm * 32 + mt * 16 + lr) * 64 + kb));
#pragma unroll
        for (int nt = 0; nt < 4; nt++)
            offB[ks][nt] = sw64((uint32_t)((wn * 64 + nt * 16 + lr) * 64 + kb));
    }

    const int nk = K / GTK;   // 32

#define GLOAD(kc_)                                                            \
    do {                                                                      \
        const uint32_t base_ = sb + ((kc_) % 3) * GSTG;                       \
        const int kbase_ = (kc_) * GTK;                                       \
        _Pragma("unroll")                                                     \
        for (int i = 0; i < 4; i++) {     /* A hi+lo */                       \
            int u     = tid + i * 256;                                        \
            int half_ = u >> 9;                                               \
            int v     = u & 511;                                              \
            int r     = v >> 2;                                               \
            int c     = v & 3;                                                \
            const __half* g = (half_ ? g_xl : g_x) + (long)(m0 + r) * K + kbase_ + c * 8; \
            uint32_t dd = base_ + (half_ ? GO_AL : GO_AH) + sw64((uint32_t)(r * 64 + c * 16)); \
            cpa16(dd, g);                                                     \
        }                                                                     \
        _Pragma("unroll")                                                     \
        for (int i = 0; i < 4; i++) {     /* B hi+lo */                       \
            int u     = tid + i * 256;                                        \
            int half_ = u >> 9;                                               \
            int v     = u & 511;                                              \
            int r     = v >> 2;                                               \
            int c     = v & 3;                                                \
            const __half* g = (half_ ? g_wg1l : g_wg1h) + (long)(n0 + r) * K + kbase_ + c * 8; \
            uint32_t dd = base_ + (half_ ? GO_BL : GO_BH) + sw64((uint32_t)(r * 64 + c * 16)); \
            cpa16(dd, g);                                                     \
        }                                                                     \
        CP_COMMIT();                                                          \
    } while (0)

    GLOAD(0);
    GLOAD(1);

    for (int kc = 0; kc < nk; kc++) {
        if (kc == nk - 1) { CP_WAIT0(); } else { CP_WAIT1(); }
        __syncthreads();
        if (kc + 2 < nk) GLOAD(kc + 2);

        const uint32_t base = sb + (kc % 3) * GSTG;
#pragma unroll
        for (int ks = 0; ks < 2; ks++) {
            uint32_t ah[2][4], al[2][4], bfrag[4][4];
#pragma unroll
            for (int mt = 0; mt < 2; mt++) {
                ldsm_x4(ah[mt], base + GO_AH + offA[ks][mt]);
                ldsm_x4(al[mt], base + GO_AL + offA[ks][mt]);
            }
#pragma unroll
            for (int nt = 0; nt < 4; nt++)
                ldsm_x4(bfrag[nt], base + GO_BH + offB[ks][nt]);
#pragma unroll
            for (int mt = 0; mt < 2; mt++)
#pragma unroll
                for (int nt = 0; nt < 4; nt++) {
                    mma_f16(acc[mt * 8 + nt * 2 + 0], ah[mt], bfrag[nt][0], bfrag[nt][2]);
                    mma_f16(acc[mt * 8 + nt * 2 + 1], ah[mt], bfrag[nt][1], bfrag[nt][3]);
                }
#pragma unroll
            for (int mt = 0; mt < 2; mt++)
#pragma unroll
                for (int nt = 0; nt < 4; nt++) {
                    mma_f16(acc[mt * 8 + nt * 2 + 0], al[mt], bfrag[nt][0], bfrag[nt][2]);
                    mma_f16(acc[mt * 8 + nt * 2 + 1], al[mt], bfrag[nt][1], bfrag[nt][3]);
                }
#pragma unroll
            for (int nt = 0; nt < 4; nt++)
                ldsm_x4(bfrag[nt], base + GO_BL + offB[ks][nt]);
#pragma unroll
            for (int mt = 0; mt < 2; mt++)
#pragma unroll
                for (int nt = 0; nt < 4; nt++) {
                    mma_f16(acc[mt * 8 + nt * 2 + 0], ah[mt], bfrag[nt][0], bfrag[nt][2]);
                    mma_f16(acc[mt * 8 + nt * 2 + 1], ah[mt], bfrag[nt][1], bfrag[nt][3]);
                }
        }
    }
#undef GLOAD

#pragma unroll
    for (int mt = 0; mt < 2; mt++) {
#pragma unroll
        for (int nt = 0; nt < 8; nt++) {
            const float* a4 = acc[mt * 8 + nt];
            int col  = n0 + wn * 64 + nt * 8 + ((lane & 3) << 1);
            float bb0 = bias[col], bb1 = bias[col + 1];
            int row0 = m0 + wm * 32 + mt * 16 + (lane >> 2);
            int row1 = row0 + 8;
            float v0 = fmaxf(a4[0] + bb0, 0.f), v1 = fmaxf(a4[1] + bb1, 0.f);
            float v2 = fmaxf(a4[2] + bb0, 0.f), v3 = fmaxf(a4[3] + bb1, 0.f);
            *reinterpret_cast<float2*>(g_g + (long)row0 * N + col) = make_float2(v0, v1);
            *reinterpret_cast<float2*>(g_g + (long)row1 * N + col) = make_float2(v2, v3);
        }
    }
}

// ---------------- pre-passes ------------------------------------------------
// x -> fp16 hi + lo; block 0 also zeroes routing counters
__global__ __launch_bounds__(256) void k_splitx(const float* __restrict__ x)
{
    if (blockIdx.x == 0 && threadIdx.x < EQ) {
        g_cnt[threadIdx.x] = 0;
        g_cursor[threadIdx.x] = 0;
    }
    long i = (long)(blockIdx.x * 256 + threadIdx.x) * 4;
    if (i >= (long)BQ * DQ) return;
    float4 v = *reinterpret_cast<const float4*>(x + i);
    __half2 h0, h1, l0, l1;
    h0.x = __float2half_rn(v.x); h0.y = __float2half_rn(v.y);
    h1.x = __float2half_rn(v.z); h1.y = __float2half_rn(v.w);
    l0.x = __float2half_rn(v.x - __half2float(h0.x));
    l0.y = __float2half_rn(v.y - __half2float(h0.y));
    l1.x = __float2half_rn(v.z - __half2float(h1.x));
    l1.y = __float2half_rn(v.w - __half2float(h1.y));
    *reinterpret_cast<uint2*>(g_x + i) = make_uint2(
        *reinterpret_cast<uint32_t*>(&h0), *reinterpret_cast<uint32_t*>(&h1));
    *reinterpret_cast<uint2*>(g_xl + i) = make_uint2(
        *reinterpret_cast<uint32_t*>(&l0), *reinterpret_cast<uint32_t*>(&l1));
}

// W [E][K][N] f32 -> Wh [E][N][K] fp16; 64k x 32n tile, 16B stores
__global__ __launch_bounds__(256) void k_splitw(
    const float* __restrict__ src, __half* __restrict__ dh, int K, int N)
{
    __shared__ float t[64][33];
    const int e  = blockIdx.z;
    const int n0 = blockIdx.x * 32;
    const int k0 = blockIdx.y * 64;
    const int tid = threadIdx.x;
    const float* S = src + (long)e * K * N;
#pragma unroll
    for (int i = 0; i < 2; i++) {
        int kr = (tid >> 3) + i * 32;
        int n4 = tid & 7;
        float4 v = *reinterpret_cast<const float4*>(S + (long)(k0 + kr) * N + n0 + n4 * 4);
        t[kr][n4 * 4 + 0] = v.x;
        t[kr][n4 * 4 + 1] = v.y;
        t[kr][n4 * 4 + 2] = v.z;
        t[kr][n4 * 4 + 3] = v.w;
    }
    __syncthreads();
    {
        int n = tid >> 3, kq = tid & 7;
        uint4 u;
        uint32_t* up = reinterpret_cast<uint32_t*>(&u);
#pragma unroll
        for (int j = 0; j < 4; j++) {
            __half2 h;
            h.x = __float2half_rn(t[kq * 8 + j * 2 + 0][n]);
            h.y = __float2half_rn(t[kq * 8 + j * 2 + 1][n]);
            up[j] = *reinterpret_cast<uint32_t*>(&h);
        }
        long o = (long)e * N * K + (long)(n0 + n) * K + k0 + kq * 8;
        *reinterpret_cast<uint4*>(dh + o) = u;
    }
}

// Wg1 [K=1024][N=512] f32 -> [N][K] fp16 hi + lo (32x32 transpose)
__global__ __launch_bounds__(256) void k_splitwg(const float* __restrict__ src)
{
    __shared__ float t[32][33];
    const int n0 = blockIdx.x * 32;
    const int k0 = blockIdx.y * 32;
    const int tid = threadIdx.x;
    {
        int kr = tid >> 3, n4 = tid & 7;
        float4 v = *reinterpret_cast<const float4*>(src + (long)(k0 + kr) * GQ + n0 + n4 * 4);
        t[kr][n4 * 4 + 0] = v.x;
        t[kr][n4 * 4 + 1] = v.y;
        t[kr][n4 * 4 + 2] = v.z;
        t[kr][n4 * 4 + 3] = v.w;
    }
    __syncthreads();
    {
        int n = tid >> 3, kq = tid & 7;
        float v0 = t[kq * 4 + 0][n], v1 = t[kq * 4 + 1][n];
        float v2 = t[kq * 4 + 2][n], v3 = t[kq * 4 + 3][n];
        __half2 h0, h1, l0, l1;
        h0.x = __float2half_rn(v0); h0.y = __float2half_rn(v1);
        h1.x = __float2half_rn(v2); h1.y = __float2half_rn(v3);
        l0.x = __float2half_rn(v0 - __half2float(h0.x));
        l0.y = __float2half_rn(v1 - __half2float(h0.y));
        l1.x = __float2half_rn(v2 - __half2float(h1.x));
        l1.y = __float2half_rn(v3 - __half2float(h1.y));
        long o = (long)(n0 + n) * DQ + k0 + kq * 4;
        *reinterpret_cast<uint2*>(g_wg1h + o) = make_uint2(
            *reinterpret_cast<uint32_t*>(&h0), *reinterpret_cast<uint32_t*>(&h1));
        *reinterpret_cast<uint2*>(g_wg1l + o) = make_uint2(
            *reinterpret_cast<uint32_t*>(&l0), *reinterpret_cast<uint32_t*>(&l1));
    }
}

// ---------------- small kernels ------------------------------------------
__global__ __launch_bounds__(128) void k_gate2(const float* __restrict__ Wg2,
                                               const float* __restrict__ bg2)
{
    int b    = blockIdx.x * 4 + (threadIdx.x >> 5);
    int lane = threadIdx.x & 31;
    const float* grow = g_g + (long)b * GQ;

    float acc[8] = {0, 0, 0, 0, 0, 0, 0, 0};
    for (int k = lane; k < GQ; k += 32) {
        float gv = grow[k];
        const float* w = Wg2 + k * 8;
#pragma unroll
        for (int e = 0; e < 8; e++) acc[e] = fmaf(gv, w[e], acc[e]);
    }
#pragma unroll
    for (int e = 0; e < 8; e++) {
#pragma unroll
        for (int o = 16; o; o >>= 1) acc[e] += __shfl_xor_sync(0xffffffffu, acc[e], o);
    }
    if (lane == 0) {
        float l[8], m = -1e30f;
#pragma unroll
        for (int e = 0; e < 8; e++) { l[e] = acc[e] + bg2[e]; m = fmaxf(m, l[e]); }
        float s = 0.f;
#pragma unroll
        for (int e = 0; e < 8; e++) { l[e] = expf(l[e] - m); s += l[e]; }
        float inv = 1.f / s;
#pragma unroll
        for (int e = 0; e < 8; e++) { l[e] *= inv; g_gatew[b * 8 + e] = l[e]; }
        int i0 = 0;
#pragma unroll
        for (int e = 1; e < 8; e++) if (l[e] > l[i0]) i0 = e;
        int i1 = -1;
#pragma unroll
        for (int e = 0; e < 8; e++) {
            if (e == i0) continue;
            if (i1 < 0 || l[e] > l[i1]) i1 = e;
        }
        float w0 = l[i0], w1 = l[i1];
        float mm = fmaxf(w0, w1);
        float e0 = expf(w0 - mm), e1 = expf(w1 - mm);
        float si = 1.f / (e0 + e1);
        g_topidx[2 * b]     = i0;
        g_topidx[2 * b + 1] = i1;
        g_topw[2 * b]       = e0 * si;
        g_topw[2 * b + 1]   = e1 * si;
        atomicAdd(&g_cnt[i0], 1);
        atomicAdd(&g_cnt[i1], 1);
    }
}

__global__ void k_offsets()
{
    if (threadIdx.x == 0) {
        int s = 0, idx = 0;
        for (int e = 0; e < EQ; e++) {
            g_off[e] = s;
            int c = g_cnt[e];
            s += c;
            int nt = (c + TM - 1) / TM;
            for (int t = 0; t < nt; t++) g_tiles[idx++] = e | (t << 8);
        }
        g_off[EQ] = s;
        g_ntiles = idx;
    }
}

__global__ void k_scatter()
{
    int b = blockIdx.x * blockDim.x + threadIdx.x;
    if (b >= BQ) return;
#pragma unroll
    for (int s = 0; s < 2; s++) {
        int e = g_topidx[2 * b + s];
        int p = g_off[e] + atomicAdd(&g_cursor[e], 1);
        g_ptok[p]         = b;
        g_pidx[2 * b + s] = p;
    }
}

__global__ __launch_bounds__(256) void k_usage()
{
    int e = blockIdx.x, t = threadIdx.x;
    __shared__ float sh[256];
    float s = 0.f;
    for (int b = t; b < BQ; b += 256) s += g_gatew[b * 8 + e];
    sh[t] = s;
    __syncthreads();
    for (int o = 128; o; o >>= 1) {
        if (t < o) sh[t] += sh[t + o];
        __syncthreads();
    }
    if (t == 0) g_usage[e] = sh[0];
}

__global__ void k_loss(float* out, int out_size)
{
    if (threadIdx.x == 0 && out_size > BQ * DOUTQ) {
        float acc = 0.f;
        for (int e = 0; e < EQ; e++) {
            float d = g_usage[e] / (float)BQ - 1.0f / (float)EQ;
            acc += d * d;
        }
        out[BQ * DOUTQ] = acc / (float)EQ;
    }
}

__global__ __launch_bounds__(256) void k_combine(float* __restrict__ out)
{
    int b  = blockIdx.x;
    int p0 = g_pidx[2 * b], p1 = g_pidx[2 * b + 1];
    float w0 = g_topw[2 * b], w1 = g_topw[2 * b + 1];
    const float4* y0 = reinterpret_cast<const float4*>(g_y + (long)p0 * DOUTQ);
    const float4* y1 = reinterpret_cast<const float4*>(g_y + (long)p1 * DOUTQ);
    float4* o = reinterpret_cast<float4*>(out + (long)b * DOUTQ);
    int t = threadIdx.x;   // 256 threads x 4 floats = 1024
    float4 a = y0[t], c = y1[t];
    o[t] = make_float4(w0 * a.x + w1 * c.x, w0 * a.y + w1 * c.y,
                       w0 * a.z + w1 * c.z, w0 * a.w + w1 * c.w);
}

// ---------------- launch --------------------------------------------------
extern "C" void kernel_launch(void* const* d_in, const int* in_sizes, int n_in,
                              void* d_out, int out_size)
{
    const float* x   = (const float*)d_in[0];
    const float* W1  = (const float*)d_in[1];
    const float* b1  = (const float*)d_in[2];
    const float* W2  = (const float*)d_in[3];
    const float* b2  = (const float*)d_in[4];
    const float* W3  = (const float*)d_in[5];
    const float* b3  = (const float*)d_in[6];
    const float* Wg1 = (const float*)d_in[7];
    const float* bg1 = (const float*)d_in[8];
    const float* Wg2 = (const float*)d_in[9];
    const float* bg2 = (const float*)d_in[10];
    float* out = (float*)d_out;

    float* p_y;
    int* p_ptok;
    __half *p_x, *p_w1h, *p_w2h, *p_w3h, *p_h1, *p_h2;
    cudaGetSymbolAddress((void**)&p_y,    g_y);
    cudaGetSymbolAddress((void**)&p_ptok, g_ptok);
    cudaGetSymbolAddress((void**)&p_x,    g_x);
    cudaGetSymbolAddress((void**)&p_w1h,  g_w1h);
    cudaGetSymbolAddress((void**)&p_w2h,  g_w2h);
    cudaGetSymbolAddress((void**)&p_w3h,  g_w3h);
    cudaGetSymbolAddress((void**)&p_h1,   g_h1);
    cudaGetSymbolAddress((void**)&p_h2,   g_h2);

    cudaFuncSetAttribute(moe_f16_gemm,
                         cudaFuncAttributeMaxDynamicSharedMemorySize, SMEM_SZ);
    cudaFuncSetAttribute(gate_f16_gemm,
                         cudaFuncAttributeMaxDynamicSharedMemorySize, GSMEM);

    // pre-convert inputs (k_splitx also zeroes routing counters)
    k_splitx<<<(BQ * DQ / 4 + 255) / 256, 256>>>(x);
    k_splitwg<<<dim3(GQ / 32, DQ / 32, 1), 256>>>(Wg1);
    k_splitw<<<dim3(HQ / 32, DQ / 64, EQ), 256>>>(W1, p_w1h, DQ, HQ);
    k_splitw<<<dim3(H2Q / 32, HQ / 64, EQ), 256>>>(W2, p_w2h, HQ, H2Q);
    k_splitw<<<dim3(DOUTQ / 32, H2Q / 64, EQ), 256>>>(W3, p_w3h, H2Q, DOUTQ);

    // gate: 3-term fp16 HMMA (fp32-accurate) -> softmax/top2/routing
    gate_f16_gemm<<<dim3(GQ / TN, BQ / TM, 1), 256, GSMEM>>>(bg1);
    k_gate2<<<BQ / 4, 128>>>(Wg2, bg2);
    k_offsets<<<1, 32>>>();
    k_scatter<<<BQ / 256, 256>>>();
    k_usage<<<EQ, 256>>>();
    k_loss<<<1, 32>>>(out, out_size);

    // expert layers
    {
        dim3 grid(HQ / TN, MAXTILES, 1);
        moe_f16_gemm<<<grid, 256, SMEM_SZ>>>(
            p_x, p_w1h, b1, p_h1, nullptr, p_ptok, DQ, HQ, 1);
    }
    {
        dim3 grid(H2Q / TN, MAXTILES, 1);
        moe_f16_gemm<<<grid, 256, SMEM_SZ>>>(
            p_h1, p_w2h, b2, p_h2, nullptr, nullptr, HQ, H2Q, 1);
    }
    {
        dim3 grid(DOUTQ / TN, MAXTILES, 1);
        moe_f16_gemm<<<grid, 256, SMEM_SZ>>>(
            p_h2, p_w3h, b3, nullptr, p_y, nullptr, H2Q, DOUTQ, 0);
    }
    k_combine<<<BQ, 256>>>(out);
}

// round 15
// speedup vs baseline: 2.7241x; 1.0025x over previous
#include <cuda_runtime.h>
#include <cuda_fp16.h>
#include <math.h>
#include <stdint.h>

// Problem constants
#define BQ    8192
#define DQ    1024
#define HQ    4096
#define H2Q   2048
#define DOUTQ 1024
#define EQ    8
#define GQ    512
#define PAIRS (BQ * 2)
#define MAXTILES (PAIRS / 128 + EQ)   // 136

// ---------------- scratch (device globals) ---------------------------------
__device__ float g_g[BQ * GQ];
__device__ float g_y [PAIRS * DOUTQ];
__device__ float g_gatew[BQ * EQ];
__device__ int   g_topidx[BQ * 2];
__device__ float g_topw [BQ * 2];
__device__ int   g_cnt[EQ];
__device__ int   g_off[EQ + 1];
__device__ int   g_cursor[EQ];
__device__ int   g_ptok[PAIRS];
__device__ int   g_pidx[BQ * 2];
__device__ float g_usage[EQ];
__device__ int   g_tiles[MAXTILES];
__device__ int   g_ntiles;

// fp16 operands
__device__ __half g_x  [BQ * DQ];          // x hi
__device__ __half g_xl [BQ * DQ];          // x lo (gate only)
__device__ __half g_wg1h[GQ * DQ];         // Wg1^T hi
__device__ __half g_wg1l[GQ * DQ];         // Wg1^T lo
__device__ __half g_w1h[EQ * DQ * HQ];
__device__ __half g_w2h[EQ * HQ * H2Q];
__device__ __half g_w3h[EQ * H2Q * DOUTQ];
__device__ __half g_h1 [PAIRS * HQ];
__device__ __half g_h2 [PAIRS * H2Q];

// ---------------- helpers ---------------------------------------------------
__device__ __forceinline__ uint32_t smem_u32(const void* p) {
    uint32_t a;
    asm("{ .reg .u64 t; cvta.to.shared.u64 t, %1; cvt.u32.u64 %0, t; }"
        : "=r"(a) : "l"(p));
    return a;
}
__device__ __forceinline__ uint32_t sw64(uint32_t off) {
    return off ^ ((off >> 3) & 0x30);
}
__device__ __forceinline__ uint32_t sw128(uint32_t off) {
    return off ^ ((off >> 3) & 0x70);
}
__device__ __forceinline__ void ldsm_x4(uint32_t* r, uint32_t addr) {
    asm volatile("ldmatrix.sync.aligned.m8n8.x4.shared.b16 {%0,%1,%2,%3}, [%4];"
                 : "=r"(r[0]), "=r"(r[1]), "=r"(r[2]), "=r"(r[3]) : "r"(addr));
}
__device__ __forceinline__ void mma_f16(float* d, const uint32_t* a,
                                        uint32_t b0, uint32_t b1) {
    asm volatile(
        "mma.sync.aligned.m16n8k16.row.col.f32.f16.f16.f32 "
        "{%0,%1,%2,%3}, {%4,%5,%6,%7}, {%8,%9}, {%0,%1,%2,%3};"
        : "+f"(d[0]), "+f"(d[1]), "+f"(d[2]), "+f"(d[3])
        : "r"(a[0]), "r"(a[1]), "r"(a[2]), "r"(a[3]), "r"(b0), "r"(b1));
}
__device__ __forceinline__ void cpa16(uint32_t d, const void* s) {
    asm volatile("cp.async.cg.shared.global [%0], [%1], 16;" :: "r"(d), "l"(s));
}
#define CP_COMMIT() asm volatile("cp.async.commit_group;" ::: "memory")
#define CP_WAIT1()  asm volatile("cp.async.wait_group 1;" ::: "memory")
#define CP_WAIT0()  asm volatile("cp.async.wait_group 0;" ::: "memory")

#define TM 128
#define TN 128

// ---------------- expert fp16 GEMM (single term, TK=64) ---------------------
#define TKE    64
#define O_A    0                 // 128 rows x 128B = 16384
#define O_B    16384
#define STG_SZ 32768
#define SMEM_SZ (3 * STG_SZ)     // 98304

__global__ __launch_bounds__(256, 2) void moe_f16_gemm(
    const __half* __restrict__ Ax,
    const __half* __restrict__ Bh,
    const float* __restrict__ bias,
    __half* __restrict__ Chf,
    float* __restrict__ Cf,
    const int* __restrict__ rowmap,
    int K, int N, int relu)
{
    extern __shared__ char smem[];
    if ((int)blockIdx.y >= g_ntiles) return;
    const int d    = g_tiles[blockIdx.y];
    const int e    = d & 255;
    const int ts   = d >> 8;
    const int mseg = g_off[e];
    const int mend = mseg + g_cnt[e];
    const int m0   = mseg + ts * TM;
    const int n0   = blockIdx.x * TN;

    const __half* Bhe = Bh + (long)e * (long)N * (long)K;
    const float* bvec = bias + (long)e * N;

    const uint32_t sb = smem_u32(smem);
    const int tid  = threadIdx.x;
    const int wid  = tid >> 5;
    const int lane = tid & 31;
    const int wm   = wid & 3;
    const int wn   = wid >> 2;

    float acc[16][4];
#pragma unroll
    for (int i = 0; i < 16; i++)
#pragma unroll
        for (int j = 0; j < 4; j++) acc[i][j] = 0.f;

    const int lr = ((lane >> 3) & 1) * 8 + (lane & 7);
    const int lc = (lane >> 4) * 16;

    uint32_t offA[2], offB[4];
#pragma unroll
    for (int mt = 0; mt < 2; mt++)
        offA[mt] = sw128((uint32_t)((wm * 32 + mt * 16 + lr) * 128 + lc));
#pragma unroll
    for (int nt = 0; nt < 4; nt++)
        offB[nt] = sw128((uint32_t)((wn * 64 + nt * 16 + lr) * 128 + lc));

    const int nk = K / TKE;

#define LOAD_CHUNK(kc_)                                                       \
    do {                                                                      \
        const uint32_t base_ = sb + ((kc_) % 3) * STG_SZ;                     \
        const int kbase_ = (kc_) * TKE;                                       \
        _Pragma("unroll")                                                     \
        for (int i = 0; i < 4; i++) {        /* A: 1024 16B chunks */         \
            int u = tid + i * 256;                                            \
            int r = u >> 3;                                                   \
            int c = u & 7;                                                    \
            int gm = m0 + r;                                                  \
            if (gm >= mend) gm = mend - 1;                                    \
            int src = rowmap ? rowmap[gm] : gm;                               \
            const __half* g = Ax + (long)src * K + kbase_ + c * 8;            \
            uint32_t dd = base_ + O_A + sw128((uint32_t)(r * 128 + c * 16));  \
            cpa16(dd, g);                                                     \
        }                                                                     \
        _Pragma("unroll")                                                     \
        for (int i = 0; i < 4; i++) {        /* B: 1024 16B chunks */         \
            int u = tid + i * 256;                                            \
            int r = u >> 3;                                                   \
            int c = u & 7;                                                    \
            const __half* g = Bhe + (long)(n0 + r) * K + kbase_ + c * 8;      \
            uint32_t dd = base_ + O_B + sw128((uint32_t)(r * 128 + c * 16));  \
            cpa16(dd, g);                                                     \
        }                                                                     \
        CP_COMMIT();                                                          \
    } while (0)

    LOAD_CHUNK(0);
    if (nk > 1) LOAD_CHUNK(1);

    for (int kc = 0; kc < nk; kc++) {
        if (kc == nk - 1) { CP_WAIT0(); } else { CP_WAIT1(); }
        __syncthreads();
        if (kc + 2 < nk) LOAD_CHUNK(kc + 2);

        const uint32_t base = sb + (kc % 3) * STG_SZ;
#pragma unroll
        for (int ks = 0; ks < 4; ks++) {
            const uint32_t kx = (uint32_t)(ks << 5);
            uint32_t af[2][4], bfrag[4][4];
#pragma unroll
            for (int mt = 0; mt < 2; mt++)
                ldsm_x4(af[mt], base + O_A + (offA[mt] ^ kx));
#pragma unroll
            for (int nt = 0; nt < 4; nt++)
                ldsm_x4(bfrag[nt], base + O_B + (offB[nt] ^ kx));
#pragma unroll
            for (int mt = 0; mt < 2; mt++)
#pragma unroll
                for (int nt = 0; nt < 4; nt++) {
                    mma_f16(acc[mt * 8 + nt * 2 + 0], af[mt], bfrag[nt][0], bfrag[nt][2]);
                    mma_f16(acc[mt * 8 + nt * 2 + 1], af[mt], bfrag[nt][1], bfrag[nt][3]);
                }
        }
    }
#undef LOAD_CHUNK

#pragma unroll
    for (int mt = 0; mt < 2; mt++) {
#pragma unroll
        for (int nt = 0; nt < 8; nt++) {
            const float* a4 = acc[mt * 8 + nt];
            int col  = n0 + wn * 64 + nt * 8 + ((lane & 3) << 1);
            float bb0 = bvec[col], bb1 = bvec[col + 1];
            int row0 = m0 + wm * 32 + mt * 16 + (lane >> 2);
            int row1 = row0 + 8;
            float v0 = a4[0] + bb0, v1 = a4[1] + bb1;
            float v2 = a4[2] + bb0, v3 = a4[3] + bb1;
            if (relu) {
                v0 = fmaxf(v0, 0.f); v1 = fmaxf(v1, 0.f);
                v2 = fmaxf(v2, 0.f); v3 = fmaxf(v3, 0.f);
            }
            if (Cf) {
                if (row0 < mend)
                    *reinterpret_cast<float2*>(Cf + (long)row0 * N + col) = make_float2(v0, v1);
                if (row1 < mend)
                    *reinterpret_cast<float2*>(Cf + (long)row1 * N + col) = make_float2(v2, v3);
            } else {
                if (row0 < mend) {
                    __half2 h;
                    h.x = __float2half_rn(v0); h.y = __float2half_rn(v1);
                    *reinterpret_cast<uint32_t*>(Chf + (long)row0 * N + col) =
                        *reinterpret_cast<uint32_t*>(&h);
                }
                if (row1 < mend) {
                    __half2 h;
                    h.x = __float2half_rn(v2); h.y = __float2half_rn(v3);
                    *reinterpret_cast<uint32_t*>(Chf + (long)row1 * N + col) =
                        *reinterpret_cast<uint32_t*>(&h);
                }
            }
        }
    }
}

// ---------------- gate layer-1 GEMM (3-term fp16, ~fp32 precision) ----------
#define GO_AH  0
#define GO_AL  8192
#define GO_BH  16384
#define GO_BL  24576
#define GSTG   32768
#define GSMEM  (3 * GSTG)        // 98304
#define GTK    32

__global__ __launch_bounds__(256, 2) void gate_f16_gemm(
    const float* __restrict__ bias)
{
    extern __shared__ char smem[];
    const int m0 = blockIdx.y * TM;
    const int n0 = blockIdx.x * TN;
    const int K  = DQ, N = GQ;

    const uint32_t sb = smem_u32(smem);
    const int tid  = threadIdx.x;
    const int wid  = tid >> 5;
    const int lane = tid & 31;
    const int wm   = wid & 3;
    const int wn   = wid >> 2;

    float acc[16][4];
#pragma unroll
    for (int i = 0; i < 16; i++)
#pragma unroll
        for (int j = 0; j < 4; j++) acc[i][j] = 0.f;

    const int lr = ((lane >> 3) & 1) * 8 + (lane & 7);
    const int lc = (lane >> 4) * 16;

    uint32_t offA[2][2], offB[2][4];
#pragma unroll
    for (int ks = 0; ks < 2; ks++) {
        const int kb = ks * 32 + lc;
#pragma unroll
        for (int mt = 0; mt < 2; mt++)
            offA[ks][mt] = sw64((uint32_t)((wm * 32 + mt * 16 + lr) * 64 + kb));
#pragma unroll
        for (int nt = 0; nt < 4; nt++)
            offB[ks][nt] = sw64((uint32_t)((wn * 64 + nt * 16 + lr) * 64 + kb));
    }

    const int nk = K / GTK;   // 32

#define GLOAD(kc_)                                                            \
    do {                                                                      \
        const uint32_t base_ = sb + ((kc_) % 3) * GSTG;                       \
        const int kbase_ = (kc_) * GTK;                                       \
        _Pragma("unroll")                                                     \
        for (int i = 0; i < 4; i++) {     /* A hi+lo */                       \
            int u     = tid + i * 256;                                        \
            int half_ = u >> 9;                                               \
            int v     = u & 511;                                              \
            int r     = v >> 2;                                               \
            int c     = v & 3;                                                \
            const __half* g = (half_ ? g_xl : g_x) + (long)(m0 + r) * K + kbase_ + c * 8; \
            uint32_t dd = base_ + (half_ ? GO_AL : GO_AH) + sw64((uint32_t)(r * 64 + c * 16)); \
            cpa16(dd, g);                                                     \
        }                                                                     \
        _Pragma("unroll")                                                     \
        for (int i = 0; i < 4; i++) {     /* B hi+lo */                       \
            int u     = tid + i * 256;                                        \
            int half_ = u >> 9;                                               \
            int v     = u & 511;                                              \
            int r     = v >> 2;                                               \
            int c     = v & 3;                                                \
            const __half* g = (half_ ? g_wg1l : g_wg1h) + (long)(n0 + r) * K + kbase_ + c * 8; \
            uint32_t dd = base_ + (half_ ? GO_BL : GO_BH) + sw64((uint32_t)(r * 64 + c * 16)); \
            cpa16(dd, g);                                                     \
        }                                                                     \
        CP_COMMIT();                                                          \
    } while (0)

    GLOAD(0);
    GLOAD(1);

    for (int kc = 0; kc < nk; kc++) {
        if (kc == nk - 1) { CP_WAIT0(); } else { CP_WAIT1(); }
        __syncthreads();
        if (kc + 2 < nk) GLOAD(kc + 2);

        const uint32_t base = sb + (kc % 3) * GSTG;
#pragma unroll
        for (int ks = 0; ks < 2; ks++) {
            uint32_t ah[2][4], al[2][4], bfrag[4][4];
#pragma unroll
            for (int mt = 0; mt < 2; mt++) {
                ldsm_x4(ah[mt], base + GO_AH + offA[ks][mt]);
                ldsm_x4(al[mt], base + GO_AL + offA[ks][mt]);
            }
#pragma unroll
            for (int nt = 0; nt < 4; nt++)
                ldsm_x4(bfrag[nt], base + GO_BH + offB[ks][nt]);
#pragma unroll
            for (int mt = 0; mt < 2; mt++)
#pragma unroll
                for (int nt = 0; nt < 4; nt++) {
                    mma_f16(acc[mt * 8 + nt * 2 + 0], ah[mt], bfrag[nt][0], bfrag[nt][2]);
                    mma_f16(acc[mt * 8 + nt * 2 + 1], ah[mt], bfrag[nt][1], bfrag[nt][3]);
                }
#pragma unroll
            for (int mt = 0; mt < 2; mt++)
#pragma unroll
                for (int nt = 0; nt < 4; nt++) {
                    mma_f16(acc[mt * 8 + nt * 2 + 0], al[mt], bfrag[nt][0], bfrag[nt][2]);
                    mma_f16(acc[mt * 8 + nt * 2 + 1], al[mt], bfrag[nt][1], bfrag[nt][3]);
                }
#pragma unroll
            for (int nt = 0; nt < 4; nt++)
                ldsm_x4(bfrag[nt], base + GO_BL + offB[ks][nt]);
#pragma unroll
            for (int mt = 0; mt < 2; mt++)
#pragma unroll
                for (int nt = 0; nt < 4; nt++) {
                    mma_f16(acc[mt * 8 + nt * 2 + 0], ah[mt], bfrag[nt][0], bfrag[nt][2]);
                    mma_f16(acc[mt * 8 + nt * 2 + 1], ah[mt], bfrag[nt][1], bfrag[nt][3]);
                }
        }
    }
#undef GLOAD

#pragma unroll
    for (int mt = 0; mt < 2; mt++) {
#pragma unroll
        for (int nt = 0; nt < 8; nt++) {
            const float* a4 = acc[mt * 8 + nt];
            int col  = n0 + wn * 64 + nt * 8 + ((lane & 3) << 1);
            float bb0 = bias[col], bb1 = bias[col + 1];
            int row0 = m0 + wm * 32 + mt * 16 + (lane >> 2);
            int row1 = row0 + 8;
            float v0 = fmaxf(a4[0] + bb0, 0.f), v1 = fmaxf(a4[1] + bb1, 0.f);
            float v2 = fmaxf(a4[2] + bb0, 0.f), v3 = fmaxf(a4[3] + bb1, 0.f);
            *reinterpret_cast<float2*>(g_g + (long)row0 * N + col) = make_float2(v0, v1);
            *reinterpret_cast<float2*>(g_g + (long)row1 * N + col) = make_float2(v2, v3);
        }
    }
}

// ---------------- pre-passes ------------------------------------------------
__global__ __launch_bounds__(256) void k_splitx(const float* __restrict__ x)
{
    if (blockIdx.x == 0 && threadIdx.x < EQ) {
        g_cnt[threadIdx.x] = 0;
        g_cursor[threadIdx.x] = 0;
    }
    long i = (long)(blockIdx.x * 256 + threadIdx.x) * 4;
    if (i >= (long)BQ * DQ) return;
    float4 v = *reinterpret_cast<const float4*>(x + i);
    __half2 h0, h1, l0, l1;
    h0.x = __float2half_rn(v.x); h0.y = __float2half_rn(v.y);
    h1.x = __float2half_rn(v.z); h1.y = __float2half_rn(v.w);
    l0.x = __float2half_rn(v.x - __half2float(h0.x));
    l0.y = __float2half_rn(v.y - __half2float(h0.y));
    l1.x = __float2half_rn(v.z - __half2float(h1.x));
    l1.y = __float2half_rn(v.w - __half2float(h1.y));
    *reinterpret_cast<uint2*>(g_x + i) = make_uint2(
        *reinterpret_cast<uint32_t*>(&h0), *reinterpret_cast<uint32_t*>(&h1));
    *reinterpret_cast<uint2*>(g_xl + i) = make_uint2(
        *reinterpret_cast<uint32_t*>(&l0), *reinterpret_cast<uint32_t*>(&l1));
}

// W [E][K][N] f32 -> Wh [E][N][K] fp16; 64k x 32n tile, 16B stores
__global__ __launch_bounds__(256) void k_splitw(
    const float* __restrict__ src, __half* __restrict__ dh, int K, int N)
{
    __shared__ float t[64][33];
    const int e  = blockIdx.z;
    const int n0 = blockIdx.x * 32;
    const int k0 = blockIdx.y * 64;
    const int tid = threadIdx.x;
    const float* S = src + (long)e * K * N;
#pragma unroll
    for (int i = 0; i < 2; i++) {
        int kr = (tid >> 3) + i * 32;
        int n4 = tid & 7;
        float4 v = *reinterpret_cast<const float4*>(S + (long)(k0 + kr) * N + n0 + n4 * 4);
        t[kr][n4 * 4 + 0] = v.x;
        t[kr][n4 * 4 + 1] = v.y;
        t[kr][n4 * 4 + 2] = v.z;
        t[kr][n4 * 4 + 3] = v.w;
    }
    __syncthreads();
    {
        int n = tid >> 3, kq = tid & 7;
        uint4 u;
        uint32_t* up = reinterpret_cast<uint32_t*>(&u);
#pragma unroll
        for (int j = 0; j < 4; j++) {
            __half2 h;
            h.x = __float2half_rn(t[kq * 8 + j * 2 + 0][n]);
            h.y = __float2half_rn(t[kq * 8 + j * 2 + 1][n]);
            up[j] = *reinterpret_cast<uint32_t*>(&h);
        }
        long o = (long)e * N * K + (long)(n0 + n) * K + k0 + kq * 8;
        *reinterpret_cast<uint4*>(dh + o) = u;
    }
}

// Wg1 [K=1024][N=512] f32 -> [N][K] fp16 hi + lo (32x32 transpose)
__global__ __launch_bounds__(256) void k_splitwg(const float* __restrict__ src)
{
    __shared__ float t[32][33];
    const int n0 = blockIdx.x * 32;
    const int k0 = blockIdx.y * 32;
    const int tid = threadIdx.x;
    {
        int kr = tid >> 3, n4 = tid & 7;
        float4 v = *reinterpret_cast<const float4*>(src + (long)(k0 + kr) * GQ + n0 + n4 * 4);
        t[kr][n4 * 4 + 0] = v.x;
        t[kr][n4 * 4 + 1] = v.y;
        t[kr][n4 * 4 + 2] = v.z;
        t[kr][n4 * 4 + 3] = v.w;
    }
    __syncthreads();
    {
        int n = tid >> 3, kq = tid & 7;
        float v0 = t[kq * 4 + 0][n], v1 = t[kq * 4 + 1][n];
        float v2 = t[kq * 4 + 2][n], v3 = t[kq * 4 + 3][n];
        __half2 h0, h1, l0, l1;
        h0.x = __float2half_rn(v0); h0.y = __float2half_rn(v1);
        h1.x = __float2half_rn(v2); h1.y = __float2half_rn(v3);
        l0.x = __float2half_rn(v0 - __half2float(h0.x));
        l0.y = __float2half_rn(v1 - __half2float(h0.y));
        l1.x = __float2half_rn(v2 - __half2float(h1.x));
        l1.y = __float2half_rn(v3 - __half2float(h1.y));
        long o = (long)(n0 + n) * DQ + k0 + kq * 4;
        *reinterpret_cast<uint2*>(g_wg1h + o) = make_uint2(
            *reinterpret_cast<uint32_t*>(&h0), *reinterpret_cast<uint32_t*>(&h1));
        *reinterpret_cast<uint2*>(g_wg1l + o) = make_uint2(
            *reinterpret_cast<uint32_t*>(&l0), *reinterpret_cast<uint32_t*>(&l1));
    }
}

// ---------------- small kernels ------------------------------------------
__global__ __launch_bounds__(128) void k_gate2(const float* __restrict__ Wg2,
                                               const float* __restrict__ bg2)
{
    int b    = blockIdx.x * 4 + (threadIdx.x >> 5);
    int lane = threadIdx.x & 31;
    const float* grow = g_g + (long)b * GQ;

    float acc[8] = {0, 0, 0, 0, 0, 0, 0, 0};
    for (int k = lane; k < GQ; k += 32) {
        float gv = grow[k];
        const float* w = Wg2 + k * 8;
#pragma unroll
        for (int e = 0; e < 8; e++) acc[e] = fmaf(gv, w[e], acc[e]);
    }
#pragma unroll
    for (int e = 0; e < 8; e++) {
#pragma unroll
        for (int o = 16; o; o >>= 1) acc[e] += __shfl_xor_sync(0xffffffffu, acc[e], o);
    }
    if (lane == 0) {
        float l[8], m = -1e30f;
#pragma unroll
        for (int e = 0; e < 8; e++) { l[e] = acc[e] + bg2[e]; m = fmaxf(m, l[e]); }
        float s = 0.f;
#pragma unroll
        for (int e = 0; e < 8; e++) { l[e] = expf(l[e] - m); s += l[e]; }
        float inv = 1.f / s;
#pragma unroll
        for (int e = 0; e < 8; e++) { l[e] *= inv; g_gatew[b * 8 + e] = l[e]; }
        int i0 = 0;
#pragma unroll
        for (int e = 1; e < 8; e++) if (l[e] > l[i0]) i0 = e;
        int i1 = -1;
#pragma unroll
        for (int e = 0; e < 8; e++) {
            if (e == i0) continue;
            if (i1 < 0 || l[e] > l[i1]) i1 = e;
        }
        float w0 = l[i0], w1 = l[i1];
        float mm = fmaxf(w0, w1);
        float e0 = expf(w0 - mm), e1 = expf(w1 - mm);
        float si = 1.f / (e0 + e1);
        g_topidx[2 * b]     = i0;
        g_topidx[2 * b + 1] = i1;
        g_topw[2 * b]       = e0 * si;
        g_topw[2 * b + 1]   = e1 * si;
        atomicAdd(&g_cnt[i0], 1);
        atomicAdd(&g_cnt[i1], 1);
    }
}

__global__ void k_offsets()
{
    if (threadIdx.x == 0) {
        int s = 0, idx = 0;
        for (int e = 0; e < EQ; e++) {
            g_off[e] = s;
            int c = g_cnt[e];
            s += c;
            int nt = (c + TM - 1) / TM;
            for (int t = 0; t < nt; t++) g_tiles[idx++] = e | (t << 8);
        }
        g_off[EQ] = s;
        g_ntiles = idx;
    }
}

__global__ void k_scatter()
{
    int b = blockIdx.x * blockDim.x + threadIdx.x;
    if (b >= BQ) return;
#pragma unroll
    for (int s = 0; s < 2; s++) {
        int e = g_topidx[2 * b + s];
        int p = g_off[e] + atomicAdd(&g_cursor[e], 1);
        g_ptok[p]         = b;
        g_pidx[2 * b + s] = p;
    }
}

__global__ __launch_bounds__(256) void k_usage()
{
    int e = blockIdx.x, t = threadIdx.x;
    __shared__ float sh[256];
    float s = 0.f;
    for (int b = t; b < BQ; b += 256) s += g_gatew[b * 8 + e];
    sh[t] = s;
    __syncthreads();
    for (int o = 128; o; o >>= 1) {
        if (t < o) sh[t] += sh[t + o];
        __syncthreads();
    }
    if (t == 0) g_usage[e] = sh[0];
}

__global__ void k_loss(float* out, int out_size)
{
    if (threadIdx.x == 0 && out_size > BQ * DOUTQ) {
        float acc = 0.f;
        for (int e = 0; e < EQ; e++) {
            float d = g_usage[e] / (float)BQ - 1.0f / (float)EQ;
            acc += d * d;
        }
        out[BQ * DOUTQ] = acc / (float)EQ;
    }
}

__global__ __launch_bounds__(256) void k_combine(float* __restrict__ out)
{
    int b  = blockIdx.x;
    int p0 = g_pidx[2 * b], p1 = g_pidx[2 * b + 1];
    float w0 = g_topw[2 * b], w1 = g_topw[2 * b + 1];
    const float4* y0 = reinterpret_cast<const float4*>(g_y + (long)p0 * DOUTQ);
    const float4* y1 = reinterpret_cast<const float4*>(g_y + (long)p1 * DOUTQ);
    float4* o = reinterpret_cast<float4*>(out + (long)b * DOUTQ);
    int t = threadIdx.x;   // 256 threads x 4 floats = 1024
    float4 a = y0[t], c = y1[t];
    o[t] = make_float4(w0 * a.x + w1 * c.x, w0 * a.y + w1 * c.y,
                       w0 * a.z + w1 * c.z, w0 * a.w + w1 * c.w);
}

// ---------------- launch --------------------------------------------------
extern "C" void kernel_launch(void* const* d_in, const int* in_sizes, int n_in,
                              void* d_out, int out_size)
{
    const float* x   = (const float*)d_in[0];
    const float* W1  = (const float*)d_in[1];
    const float* b1  = (const float*)d_in[2];
    const float* W2  = (const float*)d_in[3];
    const float* b2  = (const float*)d_in[4];
    const float* W3  = (const float*)d_in[5];
    const float* b3  = (const float*)d_in[6];
    const float* Wg1 = (const float*)d_in[7];
    const float* bg1 = (const float*)d_in[8];
    const float* Wg2 = (const float*)d_in[9];
    const float* bg2 = (const float*)d_in[10];
    float* out = (float*)d_out;

    float* p_y;
    int* p_ptok;
    __half *p_x, *p_w1h, *p_w2h, *p_w3h, *p_h1, *p_h2;
    cudaGetSymbolAddress((void**)&p_y,    g_y);
    cudaGetSymbolAddress((void**)&p_ptok, g_ptok);
    cudaGetSymbolAddress((void**)&p_x,    g_x);
    cudaGetSymbolAddress((void**)&p_w1h,  g_w1h);
    cudaGetSymbolAddress((void**)&p_w2h,  g_w2h);
    cudaGetSymbolAddress((void**)&p_w3h,  g_w3h);
    cudaGetSymbolAddress((void**)&p_h1,   g_h1);
    cudaGetSymbolAddress((void**)&p_h2,   g_h2);

    cudaFuncSetAttribute(moe_f16_gemm,
                         cudaFuncAttributeMaxDynamicSharedMemorySize, SMEM_SZ);
    cudaFuncSetAttribute(gate_f16_gemm,
                         cudaFuncAttributeMaxDynamicSharedMemorySize, GSMEM);

    // side stream + fork/join events (created per call; not destroyed —
    // destroying a capture-participating stream would invalidate capture,
    // and kernel_launch itself only runs a handful of times)
    cudaStream_t sB;
    cudaEvent_t evF, evJ;
    cudaStreamCreateWithFlags(&sB, cudaStreamNonBlocking);
    cudaEventCreateWithFlags(&evF, cudaEventDisableTiming);
    cudaEventCreateWithFlags(&evJ, cudaEventDisableTiming);

    // ---- fork: weight conversions on side stream (depend only on inputs)
    cudaEventRecord(evF, 0);
    cudaStreamWaitEvent(sB, evF, 0);
    k_splitw<<<dim3(HQ / 32, DQ / 64, EQ), 256, 0, sB>>>(W1, p_w1h, DQ, HQ);
    k_splitw<<<dim3(H2Q / 32, HQ / 64, EQ), 256, 0, sB>>>(W2, p_w2h, HQ, H2Q);
    k_splitw<<<dim3(DOUTQ / 32, H2Q / 64, EQ), 256, 0, sB>>>(W3, p_w3h, H2Q, DOUTQ);
    cudaEventRecord(evJ, sB);

    // ---- main stream: x/Wg1 converts + gate chain + routing
    k_splitx<<<(BQ * DQ / 4 + 255) / 256, 256>>>(x);   // also zeroes counters
    k_splitwg<<<dim3(GQ / 32, DQ / 32, 1), 256>>>(Wg1);
    gate_f16_gemm<<<dim3(GQ / TN, BQ / TM, 1), 256, GSMEM>>>(bg1);
    k_gate2<<<BQ / 4, 128>>>(Wg2, bg2);
    k_offsets<<<1, 32>>>();
    k_scatter<<<BQ / 256, 256>>>();
    k_usage<<<EQ, 256>>>();
    k_loss<<<1, 32>>>(out, out_size);

    // ---- join: expert layers need converted weights
    cudaStreamWaitEvent(0, evJ, 0);

    {
        dim3 grid(HQ / TN, MAXTILES, 1);
        moe_f16_gemm<<<grid, 256, SMEM_SZ>>>(
            p_x, p_w1h, b1, p_h1, nullptr, p_ptok, DQ, HQ, 1);
    }
    {
        dim3 grid(H2Q / TN, MAXTILES, 1);
        moe_f16_gemm<<<grid, 256, SMEM_SZ>>>(
            p_h1, p_w2h, b2, p_h2, nullptr, nullptr, HQ, H2Q, 1);
    }
    {
        dim3 grid(DOUTQ / TN, MAXTILES, 1);
        moe_f16_gemm<<<grid, 256, SMEM_SZ>>>(
            p_h2, p_w3h, b3, nullptr, p_y, nullptr, H2Q, DOUTQ, 0);
    }
    k_combine<<<BQ, 256>>>(out);
}